// round 3
// baseline (speedup 1.0000x reference)
#include <cuda_runtime.h>
#include <cuda_bf16.h>
#include <math.h>

#define NN 50000
#define NE 1600000
#define DD 128
#define HC 64   // H*C = 2*32

// ---------------- scratch (no allocation allowed) ----------------
__device__ float  g_xs[2][NN * HC];     // side0: h@W_src, side1: t@W_src
__device__ float2 g_als[2][NN];         // x·(W_src@att_src) per head, per side
__device__ float2 g_ald[2][NN];         // indexed by DIRECTION: ald of that dir's dst nodes
__device__ float4 g_wv[DD];             // {ws_h0, ws_h1, wd_h0, wd_h1}
__device__ int    g_cnt[2][NN];
__device__ int    g_start[2][NN];
__device__ int    g_wptr[2][NN];
__device__ int    g_adj[2][NE];
__device__ int    g_is64;               // 1 if edge_index is int64, 0 if int32

__device__ __forceinline__ float eluf(float x) {
    return x > 0.f ? x : (__expf(x) - 1.f);
}
__device__ __forceinline__ float lrelu(float a) {
    return a > 0.f ? a : 0.2f * a;
}

// decode edge e -> (s, d) honoring detected dtype
__device__ __forceinline__ void load_edge(const void* ei, int e, int is64, int& s, int& d) {
    if (is64) {
        const long long* p = (const long long*)ei;
        s = (int)p[e];
        d = (int)p[NE + e];
    } else {
        const int* p = (const int*)ei;
        s = p[e];
        d = p[NE + e];
    }
}

// ---------------- 0. dtype detection ----------------
// If data is int64 with values < 2^31, every odd int32 word is 0.
__global__ void k_detect(const void* ei) {
    const int* p = (const int*)ei;
    int nz = 0;
    for (int i = 0; i < 64; i++) nz |= p[2 * i + 1];
    g_is64 = (nz == 0) ? 1 : 0;
}

// ---------------- 1. zero counters ----------------
__global__ void k_zero() {
    int i = blockIdx.x * blockDim.x + threadIdx.x;
    if (i < 2 * NN) ((int*)g_cnt)[i] = 0;
}

// ---------------- 2. degree histogram ----------------
// dir0: t_rep, dst = t-node (dst column). dir1: h_rep, dst = h-node (src column).
__global__ void k_hist(const void* __restrict__ ei) {
    int e = blockIdx.x * blockDim.x + threadIdx.x;
    int is64 = g_is64;
    if (e < NE) {
        int s, d;
        load_edge(ei, e, is64, s, d);
        if ((unsigned)s < NN && (unsigned)d < NN) {
            atomicAdd(&g_cnt[0][d], 1);
            atomicAdd(&g_cnt[1][s], 1);
        }
    }
}

// ---------------- 3. exclusive prefix scan (one block per direction) ----------------
__global__ void k_scan() {
    int dir = blockIdx.x;
    __shared__ int sh[1024];
    __shared__ int carry;
    int tid = threadIdx.x;
    if (tid == 0) carry = 0;
    __syncthreads();
    for (int base = 0; base < NN; base += 1024) {
        int i = base + tid;
        int v = (i < NN) ? g_cnt[dir][i] : 0;
        int x = v;
        #pragma unroll
        for (int off = 1; off < 1024; off <<= 1) {
            sh[tid] = x;
            __syncthreads();
            if (tid >= off) x += sh[tid - off];
            __syncthreads();
        }
        if (i < NN) {
            int excl = carry + x - v;
            g_start[dir][i] = excl;
            g_wptr[dir][i]  = excl;
        }
        __syncthreads();
        if (tid == 1023) carry += x;
        __syncthreads();
    }
}

// ---------------- 4. scatter edges into CSR ----------------
__global__ void k_scatter(const void* __restrict__ ei) {
    int e = blockIdx.x * blockDim.x + threadIdx.x;
    int is64 = g_is64;
    if (e < NE) {
        int s, d;
        load_edge(ei, e, is64, s, d);
        if ((unsigned)s < NN && (unsigned)d < NN) {
            int p0 = atomicAdd(&g_wptr[0][d], 1);
            g_adj[0][p0] = s;              // neighbors of t-node d are h-nodes
            int p1 = atomicAdd(&g_wptr[1][s], 1);
            g_adj[1][p1] = d;              // neighbors of h-node s are t-nodes
        }
    }
}

// ---------------- 5. fused attention-vector precompute ----------------
// wv[k] = { (W_src@att_src)[k,h0], [k,h1], (W_dst@att_dst)[k,h0], [k,h1] }
__global__ void k_prep(const float* __restrict__ Wsrc, const float* __restrict__ Wdst,
                       const float* __restrict__ attS, const float* __restrict__ attD) {
    int k = threadIdx.x;   // 128 threads
    float a0 = 0.f, a1 = 0.f, a2 = 0.f, a3 = 0.f;
    #pragma unroll 8
    for (int c = 0; c < 32; c++) {
        a0 = fmaf(Wsrc[k * 64 + c],      attS[c],      a0);
        a1 = fmaf(Wsrc[k * 64 + 32 + c], attS[32 + c], a1);
        a2 = fmaf(Wdst[k * 64 + c],      attD[c],      a2);
        a3 = fmaf(Wdst[k * 64 + 32 + c], attD[32 + c], a3);
    }
    g_wv[k] = make_float4(a0, a1, a2, a3);
}

// ---------------- 6. attention coefficients: one warp per row ----------------
// side0 = h: writes g_als[0] and g_ald[dir=1]; side1 = t: g_als[1], g_ald[0]
__global__ void k_att(const float* __restrict__ hx, const float* __restrict__ tx) {
    int side = blockIdx.y;
    const float* X = side ? tx : hx;
    int row = blockIdx.x * (blockDim.x >> 5) + (threadIdx.x >> 5);
    if (row >= NN) return;
    int lane = threadIdx.x & 31;

    float4 x = ((const float4*)X)[row * 32 + lane];
    x.x = eluf(x.x); x.y = eluf(x.y); x.z = eluf(x.z); x.w = eluf(x.w);

    float4 w0 = g_wv[lane * 4 + 0];
    float4 w1 = g_wv[lane * 4 + 1];
    float4 w2 = g_wv[lane * 4 + 2];
    float4 w3 = g_wv[lane * 4 + 3];
    float4 acc;
    acc.x = x.x * w0.x + x.y * w1.x + x.z * w2.x + x.w * w3.x;
    acc.y = x.x * w0.y + x.y * w1.y + x.z * w2.y + x.w * w3.y;
    acc.z = x.x * w0.z + x.y * w1.z + x.z * w2.z + x.w * w3.z;
    acc.w = x.x * w0.w + x.y * w1.w + x.z * w2.w + x.w * w3.w;
    #pragma unroll
    for (int off = 16; off; off >>= 1) {
        acc.x += __shfl_xor_sync(0xffffffffu, acc.x, off);
        acc.y += __shfl_xor_sync(0xffffffffu, acc.y, off);
        acc.z += __shfl_xor_sync(0xffffffffu, acc.z, off);
        acc.w += __shfl_xor_sync(0xffffffffu, acc.w, off);
    }
    if (lane == 0) {
        g_als[side][row]     = make_float2(acc.x, acc.y);
        g_ald[side ^ 1][row] = make_float2(acc.z, acc.w);
    }
}

// ---------------- 7. elu + x @ W_src (xs tables) ----------------
// 256 thr, 8 warps, 32 rows/block-tile, 4 rows/warp, 2 cols/lane. Static smem 48KB.
__global__ void k_gemm(const float* __restrict__ hx, const float* __restrict__ tx,
                       const float* __restrict__ Wsrc) {
    __shared__ float Wc[128 * 64];   // [k][c]   32KB
    __shared__ float xt[32 * 128];   // [row][k] 16KB
    int side = blockIdx.y;
    const float* X = side ? tx : hx;
    float* XS = g_xs[side];

    int tid = threadIdx.x;
    for (int i = tid; i < 128 * 64; i += 256) Wc[i] = Wsrc[i];

    int warp = tid >> 5, lane = tid & 31;
    int ntiles = (NN + 31) / 32;
    for (int tile = blockIdx.x; tile < ntiles; tile += gridDim.x) {
        __syncthreads();
        int r0 = tile * 32;
        for (int i = tid; i < 32 * 32; i += 256) {   // 32 rows x 32 float4
            int row = i >> 5, q = i & 31;
            float4 v = make_float4(0.f, 0.f, 0.f, 0.f);
            int gr = r0 + row;
            if (gr < NN) v = ((const float4*)X)[gr * 32 + q];
            v.x = eluf(v.x); v.y = eluf(v.y); v.z = eluf(v.z); v.w = eluf(v.w);
            ((float4*)xt)[i] = v;
        }
        __syncthreads();

        int rb = warp * 4;
        const float* xr = xt + rb * 128;
        float2 a0 = {0.f,0.f}, a1 = {0.f,0.f}, a2 = {0.f,0.f}, a3 = {0.f,0.f};
        #pragma unroll 8
        for (int k = 0; k < 128; k += 4) {
            float4 x0 = *(const float4*)&xr[k];
            float4 x1 = *(const float4*)&xr[128 + k];
            float4 x2 = *(const float4*)&xr[256 + k];
            float4 x3 = *(const float4*)&xr[384 + k];
            #pragma unroll
            for (int j = 0; j < 4; j++) {
                float2 w = *(const float2*)&Wc[(k + j) * 64 + lane * 2];
                float v0 = j == 0 ? x0.x : j == 1 ? x0.y : j == 2 ? x0.z : x0.w;
                float v1 = j == 0 ? x1.x : j == 1 ? x1.y : j == 2 ? x1.z : x1.w;
                float v2 = j == 0 ? x2.x : j == 1 ? x2.y : j == 2 ? x2.z : x2.w;
                float v3 = j == 0 ? x3.x : j == 1 ? x3.y : j == 2 ? x3.z : x3.w;
                a0.x = fmaf(v0, w.x, a0.x); a0.y = fmaf(v0, w.y, a0.y);
                a1.x = fmaf(v1, w.x, a1.x); a1.y = fmaf(v1, w.y, a1.y);
                a2.x = fmaf(v2, w.x, a2.x); a2.y = fmaf(v2, w.y, a2.y);
                a3.x = fmaf(v3, w.x, a3.x); a3.y = fmaf(v3, w.y, a3.y);
            }
        }
        int g = r0 + rb;
        if (g + 0 < NN) ((float2*)XS)[(g + 0) * 32 + lane] = a0;
        if (g + 1 < NN) ((float2*)XS)[(g + 1) * 32 + lane] = a1;
        if (g + 2 < NN) ((float2*)XS)[(g + 2) * 32 + lane] = a2;
        if (g + 3 < NN) ((float2*)XS)[(g + 3) * 32 + lane] = a3;
    }
}

// ---------------- 8. per-destination online-softmax aggregation ----------------
// one warp per dst node; lanes 0-15 = edge A channels (4 ch/lane), lanes 16-31 = edge B
__global__ void k_agg(const float* __restrict__ bias, float* __restrict__ out) {
    int dir = blockIdx.y;
    int n = blockIdx.x * (blockDim.x >> 5) + (threadIdx.x >> 5);
    if (n >= NN) return;
    int lane = threadIdx.x & 31;
    int ch4 = lane & 15;                 // float4 index: channels 4*ch4..4*ch4+3
    bool head1 = (lane & 8) != 0;        // ch4 >= 8 -> channels 32..63 -> head 1
    bool hiEdge = lane >= 16;

    // side of SOURCE features for this direction: dir0 src=h(side0), dir1 src=t(side1)
    const float*  xs  = g_xs[dir];
    const float2* als = g_als[dir];
    float2 aldn = g_ald[dir][n];
    float2 alsn = als[n];

    // self loop initializes the online softmax state
    float m0 = lrelu(alsn.x + aldn.x);
    float m1 = lrelu(alsn.y + aldn.y);
    float s0 = 1.f, s1 = 1.f;
    float4 acc = make_float4(0.f, 0.f, 0.f, 0.f);
    if (!hiEdge) acc = ((const float4*)xs)[n * 16 + ch4];

    int start = g_start[dir][n];
    int deg   = g_cnt[dir][n];
    const int* adj = g_adj[dir] + start;

    for (int base = 0; base < deg; base += 32) {
        int j = base + lane;
        int sv = 0;
        float e0 = -1e30f, e1 = -1e30f;
        if (j < deg) {
            sv = adj[j];
            float2 a = als[sv];
            e0 = lrelu(a.x + aldn.x);
            e1 = lrelu(a.y + aldn.y);
        }
        float c0 = e0, c1 = e1;
        #pragma unroll
        for (int off = 16; off; off >>= 1) {
            c0 = fmaxf(c0, __shfl_xor_sync(0xffffffffu, c0, off));
            c1 = fmaxf(c1, __shfl_xor_sync(0xffffffffu, c1, off));
        }
        float nm0 = fmaxf(m0, c0), nm1 = fmaxf(m1, c1);
        float sc0 = __expf(m0 - nm0), sc1 = __expf(m1 - nm1);
        float p0 = __expf(e0 - nm0);     // ~0 for invalid lanes
        float p1 = __expf(e1 - nm1);
        float t0 = p0, t1 = p1;
        #pragma unroll
        for (int off = 16; off; off >>= 1) {
            t0 += __shfl_xor_sync(0xffffffffu, t0, off);
            t1 += __shfl_xor_sync(0xffffffffu, t1, off);
        }
        s0 = s0 * sc0 + t0;
        s1 = s1 * sc1 + t1;
        float sc = head1 ? sc1 : sc0;
        acc.x *= sc; acc.y *= sc; acc.z *= sc; acc.w *= sc;
        m0 = nm0; m1 = nm1;

        int cnt = min(32, deg - base);
        for (int i = 0; i < cnt; i += 2) {
            int  sA  = __shfl_sync(0xffffffffu, sv, i);
            int  sB  = __shfl_sync(0xffffffffu, sv, i + 1);
            float pA0 = __shfl_sync(0xffffffffu, p0, i);
            float pA1 = __shfl_sync(0xffffffffu, p1, i);
            float pB0 = __shfl_sync(0xffffffffu, p0, i + 1);
            float pB1 = __shfl_sync(0xffffffffu, p1, i + 1);
            int   s  = hiEdge ? sB : sA;
            float w  = hiEdge ? (head1 ? pB1 : pB0) : (head1 ? pA1 : pA0);
            float4 xv = ((const float4*)xs)[s * 16 + ch4];
            acc.x = fmaf(w, xv.x, acc.x);
            acc.y = fmaf(w, xv.y, acc.y);
            acc.z = fmaf(w, xv.z, acc.z);
            acc.w = fmaf(w, xv.w, acc.w);
        }
    }

    // combine the two half-warp edge accumulators
    acc.x += __shfl_xor_sync(0xffffffffu, acc.x, 16);
    acc.y += __shfl_xor_sync(0xffffffffu, acc.y, 16);
    acc.z += __shfl_xor_sync(0xffffffffu, acc.z, 16);
    acc.w += __shfl_xor_sync(0xffffffffu, acc.w, 16);

    if (lane < 16) {
        float inv = 1.f / ((head1 ? s1 : s0) + 1e-16f);
        float4 b = ((const float4*)bias)[ch4];
        float4 o;
        o.x = acc.x * inv + b.x;
        o.y = acc.y * inv + b.y;
        o.z = acc.z * inv + b.z;
        o.w = acc.w * inv + b.w;
        // dir0 = t_rep (second half of out), dir1 = h_rep (first half)
        float* op = out + (dir == 0 ? (size_t)NN * 64 : 0) + (size_t)n * 64;
        ((float4*)op)[ch4] = o;
    }
}

// ---------------- launch ----------------
extern "C" void kernel_launch(void* const* d_in, const int* in_sizes, int n_in,
                              void* d_out, int out_size) {
    const float* hx   = (const float*)d_in[0];
    const float* tx   = (const float*)d_in[1];
    const void*  ei   = d_in[2];
    const float* Wsrc = (const float*)d_in[3];
    const float* Wdst = (const float*)d_in[4];
    const float* attS = (const float*)d_in[5];
    const float* attD = (const float*)d_in[6];
    const float* bias = (const float*)d_in[7];
    float* out = (float*)d_out;

    k_detect<<<1, 1>>>(ei);
    k_zero<<<(2 * NN + 255) / 256, 256>>>();
    k_hist<<<(NE + 255) / 256, 256>>>(ei);
    k_scan<<<2, 1024>>>();
    k_scatter<<<(NE + 255) / 256, 256>>>(ei);
    k_prep<<<1, 128>>>(Wsrc, Wdst, attS, attD);
    k_att<<<dim3((NN + 7) / 8, 2), 256>>>(hx, tx);
    k_gemm<<<dim3(296, 2), 256>>>(hx, tx, Wsrc);
    k_agg<<<dim3((NN + 7) / 8, 2), 256>>>(bias, out);
}

// round 4
// speedup vs baseline: 1.2072x; 1.2072x over previous
#include <cuda_runtime.h>
#include <cuda_bf16.h>
#include <math.h>

#define NN 50000
#define NE 1600000
#define DD 128
#define HC 64   // H*C = 2*32
#define SCAN_BLK 1024
#define NSCAN_BLK ((NN + SCAN_BLK - 1) / SCAN_BLK)   // 49

// ---------------- scratch (no allocation allowed) ----------------
__device__ float  g_xs[2][NN * HC];     // side0: h@W_src, side1: t@W_src
__device__ float2 g_als[2][NN];         // x·(W_src@att_src) per head, per side
__device__ float2 g_ald[2][NN];         // indexed by DIRECTION: ald of that dir's dst nodes
__device__ float4 g_wv[DD];             // {ws_h0, ws_h1, wd_h0, wd_h1}
__device__ int    g_cnt[2][NN];
__device__ int    g_start[2][NN];
__device__ int    g_wptr[2][NN];
__device__ int    g_adj[2][NE];
__device__ int    g_bsum[2][NSCAN_BLK];
__device__ int    g_is64;               // 1 if edge_index is int64, 0 if int32

__device__ __forceinline__ float eluf(float x) {
    return x > 0.f ? x : (__expf(x) - 1.f);
}
__device__ __forceinline__ float lrelu(float a) {
    return a > 0.f ? a : 0.2f * a;
}

// decode edge e -> (s, d) honoring detected dtype
__device__ __forceinline__ void load_edge(const void* ei, int e, int is64, int& s, int& d) {
    if (is64) {
        const long long* p = (const long long*)ei;
        s = (int)p[e];
        d = (int)p[NE + e];
    } else {
        const int* p = (const int*)ei;
        s = p[e];
        d = p[NE + e];
    }
}

// ---------------- 0. dtype detection ----------------
// If data is int64 with values < 2^31, every odd int32 word is 0.
__global__ void k_detect(const void* ei) {
    const int* p = (const int*)ei;
    int nz = 0;
    for (int i = 0; i < 64; i++) nz |= p[2 * i + 1];
    g_is64 = (nz == 0) ? 1 : 0;
}

// ---------------- 1. zero counters ----------------
__global__ void k_zero() {
    int i = blockIdx.x * blockDim.x + threadIdx.x;
    if (i < 2 * NN) ((int*)g_cnt)[i] = 0;
}

// ---------------- 2. degree histogram ----------------
// dir0: t_rep, dst = t-node (dst column). dir1: h_rep, dst = h-node (src column).
__global__ void k_hist(const void* __restrict__ ei) {
    int e = blockIdx.x * blockDim.x + threadIdx.x;
    int is64 = g_is64;
    if (e < NE) {
        int s, d;
        load_edge(ei, e, is64, s, d);
        if ((unsigned)s < NN && (unsigned)d < NN) {
            atomicAdd(&g_cnt[0][d], 1);
            atomicAdd(&g_cnt[1][s], 1);
        }
    }
}

// ---------------- 3a. per-block scan (shfl warp scan) ----------------
__global__ void k_scan1() {
    __shared__ int wsum[32];
    int dir = blockIdx.y;
    int tid = threadIdx.x;
    int lane = tid & 31, warp = tid >> 5;
    int i = blockIdx.x * SCAN_BLK + tid;
    int v = (i < NN) ? g_cnt[dir][i] : 0;
    int x = v;
    #pragma unroll
    for (int off = 1; off < 32; off <<= 1) {
        int y = __shfl_up_sync(0xffffffffu, x, off);
        if (lane >= off) x += y;
    }
    if (lane == 31) wsum[warp] = x;
    __syncthreads();
    if (warp == 0) {
        int w = wsum[lane];
        #pragma unroll
        for (int off = 1; off < 32; off <<= 1) {
            int y = __shfl_up_sync(0xffffffffu, w, off);
            if (lane >= off) w += y;
        }
        wsum[lane] = w - wsum[lane];     // exclusive warp offsets
        if (lane == 31) g_bsum[dir][blockIdx.x] = w;   // block total
    }
    __syncthreads();
    if (i < NN) g_start[dir][i] = x - v + wsum[warp];  // local exclusive prefix
}

// ---------------- 3b. scan the block sums (tiny) ----------------
__global__ void k_scan2() {
    int lane = threadIdx.x & 31;
    int dir = threadIdx.x >> 5;
    if (lane == 0 && dir < 2) {
        int acc = 0;
        #pragma unroll 7
        for (int b = 0; b < NSCAN_BLK; b++) {
            int t = g_bsum[dir][b];
            g_bsum[dir][b] = acc;
            acc += t;
        }
    }
}

// ---------------- 3c. add block offsets ----------------
__global__ void k_scan3() {
    int dir = blockIdx.y;
    int i = blockIdx.x * 256 + threadIdx.x;
    if (i < NN) {
        int e = g_start[dir][i] + g_bsum[dir][i / SCAN_BLK];
        g_start[dir][i] = e;
        g_wptr[dir][i]  = e;
    }
}

// ---------------- 4. scatter edges into CSR ----------------
__global__ void k_scatter(const void* __restrict__ ei) {
    int e = blockIdx.x * blockDim.x + threadIdx.x;
    int is64 = g_is64;
    if (e < NE) {
        int s, d;
        load_edge(ei, e, is64, s, d);
        if ((unsigned)s < NN && (unsigned)d < NN) {
            int p0 = atomicAdd(&g_wptr[0][d], 1);
            g_adj[0][p0] = s;              // neighbors of t-node d are h-nodes
            int p1 = atomicAdd(&g_wptr[1][s], 1);
            g_adj[1][p1] = d;              // neighbors of h-node s are t-nodes
        }
    }
}

// ---------------- 5. fused attention-vector precompute ----------------
// wv[k] = { (W_src@att_src)[k,h0], [k,h1], (W_dst@att_dst)[k,h0], [k,h1] }
__global__ void k_prep(const float* __restrict__ Wsrc, const float* __restrict__ Wdst,
                       const float* __restrict__ attS, const float* __restrict__ attD) {
    int k = threadIdx.x;   // 128 threads
    float a0 = 0.f, a1 = 0.f, a2 = 0.f, a3 = 0.f;
    #pragma unroll 8
    for (int c = 0; c < 32; c++) {
        a0 = fmaf(Wsrc[k * 64 + c],      attS[c],      a0);
        a1 = fmaf(Wsrc[k * 64 + 32 + c], attS[32 + c], a1);
        a2 = fmaf(Wdst[k * 64 + c],      attD[c],      a2);
        a3 = fmaf(Wdst[k * 64 + 32 + c], attD[32 + c], a3);
    }
    g_wv[k] = make_float4(a0, a1, a2, a3);
}

// ---------------- 6. attention coefficients: one warp per row ----------------
// side0 = h: writes g_als[0] and g_ald[dir=1]; side1 = t: g_als[1], g_ald[0]
__global__ void k_att(const float* __restrict__ hx, const float* __restrict__ tx) {
    int side = blockIdx.y;
    const float* X = side ? tx : hx;
    int row = blockIdx.x * (blockDim.x >> 5) + (threadIdx.x >> 5);
    if (row >= NN) return;
    int lane = threadIdx.x & 31;

    float4 x = ((const float4*)X)[row * 32 + lane];
    x.x = eluf(x.x); x.y = eluf(x.y); x.z = eluf(x.z); x.w = eluf(x.w);

    float4 w0 = g_wv[lane * 4 + 0];
    float4 w1 = g_wv[lane * 4 + 1];
    float4 w2 = g_wv[lane * 4 + 2];
    float4 w3 = g_wv[lane * 4 + 3];
    float4 acc;
    acc.x = x.x * w0.x + x.y * w1.x + x.z * w2.x + x.w * w3.x;
    acc.y = x.x * w0.y + x.y * w1.y + x.z * w2.y + x.w * w3.y;
    acc.z = x.x * w0.z + x.y * w1.z + x.z * w2.z + x.w * w3.z;
    acc.w = x.x * w0.w + x.y * w1.w + x.z * w2.w + x.w * w3.w;
    #pragma unroll
    for (int off = 16; off; off >>= 1) {
        acc.x += __shfl_xor_sync(0xffffffffu, acc.x, off);
        acc.y += __shfl_xor_sync(0xffffffffu, acc.y, off);
        acc.z += __shfl_xor_sync(0xffffffffu, acc.z, off);
        acc.w += __shfl_xor_sync(0xffffffffu, acc.w, off);
    }
    if (lane == 0) {
        g_als[side][row]     = make_float2(acc.x, acc.y);
        g_ald[side ^ 1][row] = make_float2(acc.z, acc.w);
    }
}

// ---------------- 7. elu + x @ W_src (xs tables) ----------------
// 256 thr, 8 warps, 32 rows/block-tile, 4 rows/warp, 2 cols/lane. Static smem 48KB.
__global__ void k_gemm(const float* __restrict__ hx, const float* __restrict__ tx,
                       const float* __restrict__ Wsrc) {
    __shared__ float Wc[128 * 64];   // [k][c]   32KB
    __shared__ float xt[32 * 128];   // [row][k] 16KB
    int side = blockIdx.y;
    const float* X = side ? tx : hx;
    float* XS = g_xs[side];

    int tid = threadIdx.x;
    for (int i = tid; i < 128 * 64; i += 256) Wc[i] = Wsrc[i];

    int warp = tid >> 5, lane = tid & 31;
    int ntiles = (NN + 31) / 32;
    for (int tile = blockIdx.x; tile < ntiles; tile += gridDim.x) {
        __syncthreads();
        int r0 = tile * 32;
        for (int i = tid; i < 32 * 32; i += 256) {   // 32 rows x 32 float4
            int row = i >> 5, q = i & 31;
            float4 v = make_float4(0.f, 0.f, 0.f, 0.f);
            int gr = r0 + row;
            if (gr < NN) v = ((const float4*)X)[gr * 32 + q];
            v.x = eluf(v.x); v.y = eluf(v.y); v.z = eluf(v.z); v.w = eluf(v.w);
            ((float4*)xt)[i] = v;
        }
        __syncthreads();

        int rb = warp * 4;
        const float* xr = xt + rb * 128;
        float2 a0 = {0.f,0.f}, a1 = {0.f,0.f}, a2 = {0.f,0.f}, a3 = {0.f,0.f};
        #pragma unroll 8
        for (int k = 0; k < 128; k += 4) {
            float4 x0 = *(const float4*)&xr[k];
            float4 x1 = *(const float4*)&xr[128 + k];
            float4 x2 = *(const float4*)&xr[256 + k];
            float4 x3 = *(const float4*)&xr[384 + k];
            #pragma unroll
            for (int j = 0; j < 4; j++) {
                float2 w = *(const float2*)&Wc[(k + j) * 64 + lane * 2];
                float v0 = j == 0 ? x0.x : j == 1 ? x0.y : j == 2 ? x0.z : x0.w;
                float v1 = j == 0 ? x1.x : j == 1 ? x1.y : j == 2 ? x1.z : x1.w;
                float v2 = j == 0 ? x2.x : j == 1 ? x2.y : j == 2 ? x2.z : x2.w;
                float v3 = j == 0 ? x3.x : j == 1 ? x3.y : j == 2 ? x3.z : x3.w;
                a0.x = fmaf(v0, w.x, a0.x); a0.y = fmaf(v0, w.y, a0.y);
                a1.x = fmaf(v1, w.x, a1.x); a1.y = fmaf(v1, w.y, a1.y);
                a2.x = fmaf(v2, w.x, a2.x); a2.y = fmaf(v2, w.y, a2.y);
                a3.x = fmaf(v3, w.x, a3.x); a3.y = fmaf(v3, w.y, a3.y);
            }
        }
        int g = r0 + rb;
        if (g + 0 < NN) ((float2*)XS)[(g + 0) * 32 + lane] = a0;
        if (g + 1 < NN) ((float2*)XS)[(g + 1) * 32 + lane] = a1;
        if (g + 2 < NN) ((float2*)XS)[(g + 2) * 32 + lane] = a2;
        if (g + 3 < NN) ((float2*)XS)[(g + 3) * 32 + lane] = a3;
    }
}

// ---------------- 8. per-destination online-softmax aggregation ----------------
// one warp per dst node; lanes 0-15 = edge A channels (4 ch/lane), lanes 16-31 = edge B
__global__ void k_agg(const float* __restrict__ bias, float* __restrict__ out) {
    int dir = blockIdx.y;
    int n = blockIdx.x * (blockDim.x >> 5) + (threadIdx.x >> 5);
    if (n >= NN) return;
    int lane = threadIdx.x & 31;
    int ch4 = lane & 15;                 // float4 index: channels 4*ch4..4*ch4+3
    bool head1 = (lane & 8) != 0;        // ch4 >= 8 -> channels 32..63 -> head 1
    bool hiEdge = lane >= 16;

    // side of SOURCE features for this direction: dir0 src=h(side0), dir1 src=t(side1)
    const float*  xs  = g_xs[dir];
    const float2* als = g_als[dir];
    float2 aldn = g_ald[dir][n];
    float2 alsn = als[n];

    // self loop initializes the online softmax state
    float m0 = lrelu(alsn.x + aldn.x);
    float m1 = lrelu(alsn.y + aldn.y);
    float s0 = 1.f, s1 = 1.f;
    float4 acc = make_float4(0.f, 0.f, 0.f, 0.f);
    if (!hiEdge) acc = ((const float4*)xs)[n * 16 + ch4];

    int start = g_start[dir][n];
    int deg   = g_cnt[dir][n];
    const int* adj = g_adj[dir] + start;

    for (int base = 0; base < deg; base += 32) {
        int j = base + lane;
        int sv = 0;
        float e0 = -1e30f, e1 = -1e30f;
        if (j < deg) {
            sv = adj[j];
            float2 a = als[sv];
            e0 = lrelu(a.x + aldn.x);
            e1 = lrelu(a.y + aldn.y);
        }
        float c0 = e0, c1 = e1;
        #pragma unroll
        for (int off = 16; off; off >>= 1) {
            c0 = fmaxf(c0, __shfl_xor_sync(0xffffffffu, c0, off));
            c1 = fmaxf(c1, __shfl_xor_sync(0xffffffffu, c1, off));
        }
        float nm0 = fmaxf(m0, c0), nm1 = fmaxf(m1, c1);
        float sc0 = __expf(m0 - nm0), sc1 = __expf(m1 - nm1);
        float p0 = __expf(e0 - nm0);     // ~0 for invalid lanes
        float p1 = __expf(e1 - nm1);
        float t0 = p0, t1 = p1;
        #pragma unroll
        for (int off = 16; off; off >>= 1) {
            t0 += __shfl_xor_sync(0xffffffffu, t0, off);
            t1 += __shfl_xor_sync(0xffffffffu, t1, off);
        }
        s0 = s0 * sc0 + t0;
        s1 = s1 * sc1 + t1;
        float sc = head1 ? sc1 : sc0;
        acc.x *= sc; acc.y *= sc; acc.z *= sc; acc.w *= sc;
        m0 = nm0; m1 = nm1;

        int cnt = min(32, deg - base);
        for (int i = 0; i < cnt; i += 2) {
            int  sA  = __shfl_sync(0xffffffffu, sv, i);
            int  sB  = __shfl_sync(0xffffffffu, sv, i + 1);
            float pA0 = __shfl_sync(0xffffffffu, p0, i);
            float pA1 = __shfl_sync(0xffffffffu, p1, i);
            float pB0 = __shfl_sync(0xffffffffu, p0, i + 1);
            float pB1 = __shfl_sync(0xffffffffu, p1, i + 1);
            int   s  = hiEdge ? sB : sA;
            float w  = hiEdge ? (head1 ? pB1 : pB0) : (head1 ? pA1 : pA0);
            float4 xv = ((const float4*)xs)[s * 16 + ch4];
            acc.x = fmaf(w, xv.x, acc.x);
            acc.y = fmaf(w, xv.y, acc.y);
            acc.z = fmaf(w, xv.z, acc.z);
            acc.w = fmaf(w, xv.w, acc.w);
        }
    }

    // combine the two half-warp edge accumulators
    acc.x += __shfl_xor_sync(0xffffffffu, acc.x, 16);
    acc.y += __shfl_xor_sync(0xffffffffu, acc.y, 16);
    acc.z += __shfl_xor_sync(0xffffffffu, acc.z, 16);
    acc.w += __shfl_xor_sync(0xffffffffu, acc.w, 16);

    if (lane < 16) {
        float inv = 1.f / ((head1 ? s1 : s0) + 1e-16f);
        float4 b = ((const float4*)bias)[ch4];
        float4 o;
        o.x = acc.x * inv + b.x;
        o.y = acc.y * inv + b.y;
        o.z = acc.z * inv + b.z;
        o.w = acc.w * inv + b.w;
        // dir0 = t_rep (second half of out), dir1 = h_rep (first half)
        float* op = out + (dir == 0 ? (size_t)NN * 64 : 0) + (size_t)n * 64;
        ((float4*)op)[ch4] = o;
    }
}

// ---------------- launch ----------------
extern "C" void kernel_launch(void* const* d_in, const int* in_sizes, int n_in,
                              void* d_out, int out_size) {
    const float* hx   = (const float*)d_in[0];
    const float* tx   = (const float*)d_in[1];
    const void*  ei   = d_in[2];
    const float* Wsrc = (const float*)d_in[3];
    const float* Wdst = (const float*)d_in[4];
    const float* attS = (const float*)d_in[5];
    const float* attD = (const float*)d_in[6];
    const float* bias = (const float*)d_in[7];
    float* out = (float*)d_out;

    k_detect<<<1, 1>>>(ei);
    k_zero<<<(2 * NN + 255) / 256, 256>>>();
    k_hist<<<(NE + 255) / 256, 256>>>(ei);
    k_scan1<<<dim3(NSCAN_BLK, 2), SCAN_BLK>>>();
    k_scan2<<<1, 64>>>();
    k_scan3<<<dim3((NN + 255) / 256, 2), 256>>>();
    k_scatter<<<(NE + 255) / 256, 256>>>(ei);
    k_prep<<<1, 128>>>(Wsrc, Wdst, attS, attD);
    k_att<<<dim3((NN + 7) / 8, 2), 256>>>(hx, tx);
    k_gemm<<<dim3(296, 2), 256>>>(hx, tx, Wsrc);
    k_agg<<<dim3((NN + 7) / 8, 2), 256>>>(bias, out);
}

// round 5
// speedup vs baseline: 1.3210x; 1.0943x over previous
#include <cuda_runtime.h>
#include <cuda_bf16.h>
#include <math.h>

#define NN 50000
#define NE 1600000
#define DD 128
#define HC 64   // H*C = 2*32
#define SCAN_BLK 1024
#define NSCAN_BLK ((NN + SCAN_BLK - 1) / SCAN_BLK)   // 49

// ---------------- scratch (no allocation allowed) ----------------
__device__ float  g_xs[2][NN * HC];     // side0: h@W_src, side1: t@W_src
__device__ float2 g_als[2][NN];         // xs·att_src per head, per side
__device__ float2 g_ald[2][NN];         // indexed by DIRECTION: ald of that dir's dst nodes
__device__ float4 g_wv[DD];             // {ws_h0, ws_h1, wd_h0, wd_h1}
__device__ int    g_cnt[2][NN];
__device__ int    g_wptr[2][NN];
__device__ int    g_adj[2][NE];
__device__ int    g_bsum[2][NSCAN_BLK];
__device__ int    g_is64;               // 1 if edge_index is int64, 0 if int32

__device__ __forceinline__ float eluf(float x) {
    return x > 0.f ? x : (__expf(x) - 1.f);
}
__device__ __forceinline__ float lrelu(float a) {
    return a > 0.f ? a : 0.2f * a;
}

// ---------------- 1. zero counters + dtype detect ----------------
// int64 with values < 2^31 => every odd int32 word is 0.
__global__ void k_init(const void* ei) {
    int i = blockIdx.x * blockDim.x + threadIdx.x;
    if (i < 2 * NN) ((int*)g_cnt)[i] = 0;
    if (blockIdx.x == 0 && threadIdx.x == 0) {
        const int4* p = (const int4*)ei;
        int nz = 0;
        #pragma unroll
        for (int k = 0; k < 32; k++) { int4 v = p[k]; nz |= v.y | v.w; }
        g_is64 = (nz == 0) ? 1 : 0;
    }
}

// ---------------- 2. degree histogram (4 edges/thread) ----------------
// dir0: t_rep, dst = t-node. dir1: h_rep, dst = h-node.
__global__ void k_hist(const void* __restrict__ ei) {
    int base = (blockIdx.x * blockDim.x + threadIdx.x) * 4;
    if (base >= NE) return;
    int s[4], d[4];
    if (g_is64) {
        const long long* p = (const long long*)ei;
        #pragma unroll
        for (int k = 0; k < 4; k++) { s[k] = (int)p[base + k]; d[k] = (int)p[NE + base + k]; }
    } else {
        const int* p = (const int*)ei;
        int4 sv = *(const int4*)(p + base);
        int4 dv = *(const int4*)(p + NE + base);
        s[0] = sv.x; s[1] = sv.y; s[2] = sv.z; s[3] = sv.w;
        d[0] = dv.x; d[1] = dv.y; d[2] = dv.z; d[3] = dv.w;
    }
    #pragma unroll
    for (int k = 0; k < 4; k++) {
        if ((unsigned)s[k] < NN && (unsigned)d[k] < NN) {
            atomicAdd(&g_cnt[0][d[k]], 1);
            atomicAdd(&g_cnt[1][s[k]], 1);
        }
    }
}

// ---------------- 3a. per-block scan (shfl warp scan) ----------------
__global__ void k_scan1() {
    __shared__ int wsum[32];
    int dir = blockIdx.y;
    int tid = threadIdx.x;
    int lane = tid & 31, warp = tid >> 5;
    int i = blockIdx.x * SCAN_BLK + tid;
    int v = (i < NN) ? g_cnt[dir][i] : 0;
    int x = v;
    #pragma unroll
    for (int off = 1; off < 32; off <<= 1) {
        int y = __shfl_up_sync(0xffffffffu, x, off);
        if (lane >= off) x += y;
    }
    if (lane == 31) wsum[warp] = x;
    __syncthreads();
    if (warp == 0) {
        int w = wsum[lane];
        #pragma unroll
        for (int off = 1; off < 32; off <<= 1) {
            int y = __shfl_up_sync(0xffffffffu, w, off);
            if (lane >= off) w += y;
        }
        wsum[lane] = w - wsum[lane];     // exclusive warp offsets
        if (lane == 31) g_bsum[dir][blockIdx.x] = w;   // block total
    }
    __syncthreads();
    if (i < NN) g_wptr[dir][i] = x - v + wsum[warp];   // local exclusive prefix
}

// ---------------- 3b. scan the block sums (tiny) ----------------
__global__ void k_scan2() {
    int lane = threadIdx.x & 31;
    int dir = threadIdx.x >> 5;
    if (lane == 0 && dir < 2) {
        int acc = 0;
        for (int b = 0; b < NSCAN_BLK; b++) {
            int t = g_bsum[dir][b];
            g_bsum[dir][b] = acc;
            acc += t;
        }
    }
}

// ---------------- 3c. add block offsets ----------------
__global__ void k_scan3() {
    int dir = blockIdx.y;
    int i = blockIdx.x * 256 + threadIdx.x;
    if (i < NN) g_wptr[dir][i] += g_bsum[dir][i / SCAN_BLK];
}

// ---------------- 4. scatter edges into CSR (4 edges/thread) ----------------
__global__ void k_scatter(const void* __restrict__ ei) {
    int base = (blockIdx.x * blockDim.x + threadIdx.x) * 4;
    if (base >= NE) return;
    int s[4], d[4];
    if (g_is64) {
        const long long* p = (const long long*)ei;
        #pragma unroll
        for (int k = 0; k < 4; k++) { s[k] = (int)p[base + k]; d[k] = (int)p[NE + base + k]; }
    } else {
        const int* p = (const int*)ei;
        int4 sv = *(const int4*)(p + base);
        int4 dv = *(const int4*)(p + NE + base);
        s[0] = sv.x; s[1] = sv.y; s[2] = sv.z; s[3] = sv.w;
        d[0] = dv.x; d[1] = dv.y; d[2] = dv.z; d[3] = dv.w;
    }
    #pragma unroll
    for (int k = 0; k < 4; k++) {
        if ((unsigned)s[k] < NN && (unsigned)d[k] < NN) {
            int p0 = atomicAdd(&g_wptr[0][d[k]], 1);
            g_adj[0][p0] = s[k];
            int p1 = atomicAdd(&g_wptr[1][s[k]], 1);
            g_adj[1][p1] = d[k];
        }
    }
}

// ---------------- 5. fused attention-vector precompute ----------------
__global__ void k_prep(const float* __restrict__ Wsrc, const float* __restrict__ Wdst,
                       const float* __restrict__ attS, const float* __restrict__ attD) {
    int k = threadIdx.x;   // 128 threads
    float a0 = 0.f, a1 = 0.f, a2 = 0.f, a3 = 0.f;
    #pragma unroll 8
    for (int c = 0; c < 32; c++) {
        a0 = fmaf(Wsrc[k * 64 + c],      attS[c],      a0);
        a1 = fmaf(Wsrc[k * 64 + 32 + c], attS[32 + c], a1);
        a2 = fmaf(Wdst[k * 64 + c],      attD[c],      a2);
        a3 = fmaf(Wdst[k * 64 + 32 + c], attD[32 + c], a3);
    }
    g_wv[k] = make_float4(a0, a1, a2, a3);
}

// ---------------- 6. elu + x @ W_src + attention coefficients ----------------
// 256 thr, 8 warps, 32 rows/tile, 4 rows/warp, 2 cols/lane. Epilogue computes
// als (from accumulators) and ald (x · wv_dst from the smem x-tile).
__global__ void k_gemm(const float* __restrict__ hx, const float* __restrict__ tx,
                       const float* __restrict__ Wsrc, const float* __restrict__ attS) {
    __shared__ float Wc[128 * 64];   // [k][c]   32KB
    __shared__ float xt[32 * 128];   // [row][k] 16KB
    __shared__ float Av[64];         // att_src flat (h*32+c)
    int side = blockIdx.y;
    const float* X = side ? tx : hx;
    float* XS = g_xs[side];
    float2* ALS = g_als[side];
    float2* ALD = g_ald[side ^ 1];

    int tid = threadIdx.x;
    for (int i = tid; i < 128 * 64; i += 256) Wc[i] = Wsrc[i];
    if (tid < 64) Av[tid] = attS[tid];

    int warp = tid >> 5, lane = tid & 31;
    // per-lane wv_dst partials for ald (k = lane*4 .. lane*4+3)
    float4 wz, ww;
    {
        float4 w0 = g_wv[lane * 4 + 0];
        float4 w1 = g_wv[lane * 4 + 1];
        float4 w2 = g_wv[lane * 4 + 2];
        float4 w3 = g_wv[lane * 4 + 3];
        wz = make_float4(w0.z, w1.z, w2.z, w3.z);
        ww = make_float4(w0.w, w1.w, w2.w, w3.w);
    }

    int ntiles = (NN + 31) / 32;
    for (int tile = blockIdx.x; tile < ntiles; tile += gridDim.x) {
        __syncthreads();
        int r0 = tile * 32;
        for (int i = tid; i < 32 * 32; i += 256) {   // 32 rows x 32 float4
            int row = i >> 5, q = i & 31;
            float4 v = make_float4(0.f, 0.f, 0.f, 0.f);
            int gr = r0 + row;
            if (gr < NN) v = ((const float4*)X)[gr * 32 + q];
            v.x = eluf(v.x); v.y = eluf(v.y); v.z = eluf(v.z); v.w = eluf(v.w);
            ((float4*)xt)[i] = v;
        }
        __syncthreads();

        int rb = warp * 4;
        const float* xr = xt + rb * 128;
        float2 a0 = {0.f,0.f}, a1 = {0.f,0.f}, a2 = {0.f,0.f}, a3 = {0.f,0.f};
        #pragma unroll 8
        for (int k = 0; k < 128; k += 4) {
            float4 x0 = *(const float4*)&xr[k];
            float4 x1 = *(const float4*)&xr[128 + k];
            float4 x2 = *(const float4*)&xr[256 + k];
            float4 x3 = *(const float4*)&xr[384 + k];
            #pragma unroll
            for (int j = 0; j < 4; j++) {
                float2 w = *(const float2*)&Wc[(k + j) * 64 + lane * 2];
                float v0 = j == 0 ? x0.x : j == 1 ? x0.y : j == 2 ? x0.z : x0.w;
                float v1 = j == 0 ? x1.x : j == 1 ? x1.y : j == 2 ? x1.z : x1.w;
                float v2 = j == 0 ? x2.x : j == 1 ? x2.y : j == 2 ? x2.z : x2.w;
                float v3 = j == 0 ? x3.x : j == 1 ? x3.y : j == 2 ? x3.z : x3.w;
                a0.x = fmaf(v0, w.x, a0.x); a0.y = fmaf(v0, w.y, a0.y);
                a1.x = fmaf(v1, w.x, a1.x); a1.y = fmaf(v1, w.y, a1.y);
                a2.x = fmaf(v2, w.x, a2.x); a2.y = fmaf(v2, w.y, a2.y);
                a3.x = fmaf(v3, w.x, a3.x); a3.y = fmaf(v3, w.y, a3.y);
            }
        }
        int g = r0 + rb;
        if (g + 0 < NN) ((float2*)XS)[(g + 0) * 32 + lane] = a0;
        if (g + 1 < NN) ((float2*)XS)[(g + 1) * 32 + lane] = a1;
        if (g + 2 < NN) ((float2*)XS)[(g + 2) * 32 + lane] = a2;
        if (g + 3 < NN) ((float2*)XS)[(g + 3) * 32 + lane] = a3;

        // -------- epilogue: als + ald for the warp's 4 rows --------
        float avx = Av[lane * 2], avy = Av[lane * 2 + 1];
        #pragma unroll
        for (int r = 0; r < 4; r++) {
            float2 a = r == 0 ? a0 : r == 1 ? a1 : r == 2 ? a2 : a3;
            // als: sum over this head's 32 cols (lanes 0-15 = head0, 16-31 = head1)
            float v = a.x * avx + a.y * avy;
            #pragma unroll
            for (int off = 8; off; off >>= 1)
                v += __shfl_xor_sync(0xffffffffu, v, off);
            float v16 = __shfl_sync(0xffffffffu, v, 16);   // head1 sum -> all lanes

            // ald: x-row (128) dot wv_dst per head, full-warp reduce
            float4 xv = *(const float4*)&xr[r * 128 + lane * 4];
            float d0 = xv.x * wz.x + xv.y * wz.y + xv.z * wz.z + xv.w * wz.w;
            float d1 = xv.x * ww.x + xv.y * ww.y + xv.z * ww.z + xv.w * ww.w;
            #pragma unroll
            for (int off = 16; off; off >>= 1) {
                d0 += __shfl_xor_sync(0xffffffffu, d0, off);
                d1 += __shfl_xor_sync(0xffffffffu, d1, off);
            }
            if (lane == 0 && g + r < NN) {
                ALS[g + r] = make_float2(v, v16);
                ALD[g + r] = make_float2(d0, d1);
            }
        }
    }
}

// ---------------- 7. per-destination online-softmax aggregation ----------------
// one warp per dst node; lanes 0-15 = edge A channels (4 ch/lane), lanes 16-31 = edge B
__global__ void k_agg(const float* __restrict__ bias, float* __restrict__ out) {
    int dir = blockIdx.y;
    int n = blockIdx.x * (blockDim.x >> 5) + (threadIdx.x >> 5);
    if (n >= NN) return;
    int lane = threadIdx.x & 31;
    int ch4 = lane & 15;                 // float4 index: channels 4*ch4..4*ch4+3
    bool head1 = (lane & 8) != 0;        // ch4 >= 8 -> channels 32..63 -> head 1
    bool hiEdge = lane >= 16;

    const float*  xs  = g_xs[dir];
    const float2* als = g_als[dir];
    float2 aldn = g_ald[dir][n];
    float2 alsn = als[n];

    // self loop initializes the online softmax state
    float m0 = lrelu(alsn.x + aldn.x);
    float m1 = lrelu(alsn.y + aldn.y);
    float s0 = 1.f, s1 = 1.f;
    float4 acc = make_float4(0.f, 0.f, 0.f, 0.f);
    if (!hiEdge) acc = ((const float4*)xs)[n * 16 + ch4];

    int deg = g_cnt[dir][n];
    int end = g_wptr[dir][n];
    const int* adj = g_adj[dir] + (end - deg);

    for (int base = 0; base < deg; base += 32) {
        int j = base + lane;
        int sv = 0;
        float e0 = -1e30f, e1 = -1e30f;
        if (j < deg) {
            sv = adj[j];
            float2 a = als[sv];
            e0 = lrelu(a.x + aldn.x);
            e1 = lrelu(a.y + aldn.y);
        }
        float c0 = e0, c1 = e1;
        #pragma unroll
        for (int off = 16; off; off >>= 1) {
            c0 = fmaxf(c0, __shfl_xor_sync(0xffffffffu, c0, off));
            c1 = fmaxf(c1, __shfl_xor_sync(0xffffffffu, c1, off));
        }
        float nm0 = fmaxf(m0, c0), nm1 = fmaxf(m1, c1);
        float sc0 = __expf(m0 - nm0), sc1 = __expf(m1 - nm1);
        float p0 = __expf(e0 - nm0);     // ~0 for invalid lanes
        float p1 = __expf(e1 - nm1);
        float t0 = p0, t1 = p1;
        #pragma unroll
        for (int off = 16; off; off >>= 1) {
            t0 += __shfl_xor_sync(0xffffffffu, t0, off);
            t1 += __shfl_xor_sync(0xffffffffu, t1, off);
        }
        s0 = s0 * sc0 + t0;
        s1 = s1 * sc1 + t1;
        float sc = head1 ? sc1 : sc0;
        acc.x *= sc; acc.y *= sc; acc.z *= sc; acc.w *= sc;
        m0 = nm0; m1 = nm1;

        float pw = head1 ? p1 : p0;      // per-source-lane weight for my head
        int cnt = min(32, deg - base);
        int i = 0;
        // 4 edges per iteration: two independent gathers in flight
        for (; i + 4 <= cnt; i += 4) {
            int   sA = __shfl_sync(0xffffffffu, sv, hiEdge ? i + 1 : i);
            float w0A = __shfl_sync(0xffffffffu, p0, hiEdge ? i + 1 : i);
            float w1A = __shfl_sync(0xffffffffu, p1, hiEdge ? i + 1 : i);
            int   sB = __shfl_sync(0xffffffffu, sv, hiEdge ? i + 3 : i + 2);
            float w0B = __shfl_sync(0xffffffffu, p0, hiEdge ? i + 3 : i + 2);
            float w1B = __shfl_sync(0xffffffffu, p1, hiEdge ? i + 3 : i + 2);
            float4 xA = ((const float4*)xs)[sA * 16 + ch4];
            float4 xB = ((const float4*)xs)[sB * 16 + ch4];
            float wA = head1 ? w1A : w0A;
            float wB = head1 ? w1B : w0B;
            acc.x = fmaf(wA, xA.x, acc.x);
            acc.y = fmaf(wA, xA.y, acc.y);
            acc.z = fmaf(wA, xA.z, acc.z);
            acc.w = fmaf(wA, xA.w, acc.w);
            acc.x = fmaf(wB, xB.x, acc.x);
            acc.y = fmaf(wB, xB.y, acc.y);
            acc.z = fmaf(wB, xB.z, acc.z);
            acc.w = fmaf(wB, xB.w, acc.w);
        }
        for (; i < cnt; i += 2) {
            int   s = __shfl_sync(0xffffffffu, sv, hiEdge ? i + 1 : i);
            float w0 = __shfl_sync(0xffffffffu, p0, hiEdge ? i + 1 : i);
            float w1 = __shfl_sync(0xffffffffu, p1, hiEdge ? i + 1 : i);
            float w = head1 ? w1 : w0;
            if (hiEdge && i + 1 >= cnt) w = 0.f;   // odd tail: hi half idle
            float4 xv = ((const float4*)xs)[s * 16 + ch4];
            acc.x = fmaf(w, xv.x, acc.x);
            acc.y = fmaf(w, xv.y, acc.y);
            acc.z = fmaf(w, xv.z, acc.z);
            acc.w = fmaf(w, xv.w, acc.w);
        }
        (void)pw;
    }

    // combine the two half-warp edge accumulators
    acc.x += __shfl_xor_sync(0xffffffffu, acc.x, 16);
    acc.y += __shfl_xor_sync(0xffffffffu, acc.y, 16);
    acc.z += __shfl_xor_sync(0xffffffffu, acc.z, 16);
    acc.w += __shfl_xor_sync(0xffffffffu, acc.w, 16);

    if (lane < 16) {
        float inv = 1.f / ((head1 ? s1 : s0) + 1e-16f);
        float4 b = ((const float4*)bias)[ch4];
        float4 o;
        o.x = acc.x * inv + b.x;
        o.y = acc.y * inv + b.y;
        o.z = acc.z * inv + b.z;
        o.w = acc.w * inv + b.w;
        // dir0 = t_rep (second half of out), dir1 = h_rep (first half)
        float* op = out + (dir == 0 ? (size_t)NN * 64 : 0) + (size_t)n * 64;
        ((float4*)op)[ch4] = o;
    }
}

// ---------------- launch ----------------
extern "C" void kernel_launch(void* const* d_in, const int* in_sizes, int n_in,
                              void* d_out, int out_size) {
    const float* hx   = (const float*)d_in[0];
    const float* tx   = (const float*)d_in[1];
    const void*  ei   = d_in[2];
    const float* Wsrc = (const float*)d_in[3];
    const float* Wdst = (const float*)d_in[4];
    const float* attS = (const float*)d_in[5];
    const float* attD = (const float*)d_in[6];
    const float* bias = (const float*)d_in[7];
    float* out = (float*)d_out;

    k_init<<<(2 * NN + 255) / 256, 256>>>(ei);
    k_hist<<<(NE / 4 + 255) / 256, 256>>>(ei);
    k_scan1<<<dim3(NSCAN_BLK, 2), SCAN_BLK>>>();
    k_scan2<<<1, 64>>>();
    k_scan3<<<dim3((NN + 255) / 256, 2), 256>>>();
    k_scatter<<<(NE / 4 + 255) / 256, 256>>>(ei);
    k_prep<<<1, 128>>>(Wsrc, Wdst, attS, attD);
    k_gemm<<<dim3(296, 2), 256>>>(hx, tx, Wsrc, attS);
    k_agg<<<dim3((NN + 7) / 8, 2), 256>>>(bias, out);
}

// round 6
// speedup vs baseline: 1.4709x; 1.1134x over previous
#include <cuda_runtime.h>
#include <cuda_bf16.h>
#include <math.h>

#define NN 50000
#define NE 1600000
#define DD 128
#define HC 64   // H*C = 2*32
#define SCAN_BLK 1024
#define NSCAN_BLK ((NN + SCAN_BLK - 1) / SCAN_BLK)   // 49

// ---------------- scratch (no allocation allowed) ----------------
__device__ float  g_xs[2][NN * HC];     // side0: h@W_src, side1: t@W_src
__device__ float2 g_als[2][NN];         // xs·att_src per head, per side
__device__ float2 g_ald[2][NN];         // indexed by DIRECTION: ald of that dir's dst nodes
__device__ float4 g_wv[DD];             // {ws_h0, ws_h1, wd_h0, wd_h1}
__device__ int    g_cnt[2][NN];
__device__ int    g_wptr[2][NN];
__device__ int    g_adj[2][NE];
__device__ int    g_bsum[2][NSCAN_BLK];
__device__ int    g_is64;               // 1 if edge_index is int64, 0 if int32

__device__ __forceinline__ float eluf(float x) {
    return x > 0.f ? x : (__expf(x) - 1.f);
}
__device__ __forceinline__ float lrelu(float a) {
    return a > 0.f ? a : 0.2f * a;
}

__global__ void k_warm() {}

// ---------------- 1. zero counters + dtype detect ----------------
__global__ void k_init(const void* ei) {
    int i = blockIdx.x * blockDim.x + threadIdx.x;
    if (i < 2 * NN) ((int*)g_cnt)[i] = 0;
    if (blockIdx.x == 0 && threadIdx.x == 0) {
        const int4* p = (const int4*)ei;
        int nz = 0;
        #pragma unroll
        for (int k = 0; k < 32; k++) { int4 v = p[k]; nz |= v.y | v.w; }
        g_is64 = (nz == 0) ? 1 : 0;
    }
}

// ---------------- 2. degree histogram (4 edges/thread) ----------------
__global__ void k_hist(const void* __restrict__ ei) {
    int base = (blockIdx.x * blockDim.x + threadIdx.x) * 4;
    if (base >= NE) return;
    int s[4], d[4];
    if (g_is64) {
        const long long* p = (const long long*)ei;
        #pragma unroll
        for (int k = 0; k < 4; k++) { s[k] = (int)p[base + k]; d[k] = (int)p[NE + base + k]; }
    } else {
        const int* p = (const int*)ei;
        int4 sv = *(const int4*)(p + base);
        int4 dv = *(const int4*)(p + NE + base);
        s[0] = sv.x; s[1] = sv.y; s[2] = sv.z; s[3] = sv.w;
        d[0] = dv.x; d[1] = dv.y; d[2] = dv.z; d[3] = dv.w;
    }
    #pragma unroll
    for (int k = 0; k < 4; k++) {
        if ((unsigned)s[k] < NN && (unsigned)d[k] < NN) {
            atomicAdd(&g_cnt[0][d[k]], 1);
            atomicAdd(&g_cnt[1][s[k]], 1);
        }
    }
}

// ---------------- 3a. per-block scan (shfl warp scan) ----------------
__global__ void k_scan1() {
    __shared__ int wsum[32];
    int dir = blockIdx.y;
    int tid = threadIdx.x;
    int lane = tid & 31, warp = tid >> 5;
    int i = blockIdx.x * SCAN_BLK + tid;
    int v = (i < NN) ? g_cnt[dir][i] : 0;
    int x = v;
    #pragma unroll
    for (int off = 1; off < 32; off <<= 1) {
        int y = __shfl_up_sync(0xffffffffu, x, off);
        if (lane >= off) x += y;
    }
    if (lane == 31) wsum[warp] = x;
    __syncthreads();
    if (warp == 0) {
        int w = wsum[lane];
        #pragma unroll
        for (int off = 1; off < 32; off <<= 1) {
            int y = __shfl_up_sync(0xffffffffu, w, off);
            if (lane >= off) w += y;
        }
        wsum[lane] = w - wsum[lane];
        if (lane == 31) g_bsum[dir][blockIdx.x] = w;
    }
    __syncthreads();
    if (i < NN) g_wptr[dir][i] = x - v + wsum[warp];
}

// ---------------- 3b. scan the 49 block sums (warp scan) ----------------
__global__ void k_scan2() {
    __shared__ int wtot[2][2];
    int dir = threadIdx.x >> 6, t = threadIdx.x & 63;
    int lane = t & 31, w = t >> 5;
    int v = (t < NSCAN_BLK) ? g_bsum[dir][t] : 0;
    int x = v;
    #pragma unroll
    for (int off = 1; off < 32; off <<= 1) {
        int y = __shfl_up_sync(0xffffffffu, x, off);
        if (lane >= off) x += y;
    }
    if (lane == 31) wtot[dir][w] = x;
    __syncthreads();
    int add = (w == 1) ? wtot[dir][0] : 0;
    if (t < NSCAN_BLK) g_bsum[dir][t] = x - v + add;   // exclusive
}

// ---------------- 3c. add block offsets ----------------
__global__ void k_scan3() {
    int dir = blockIdx.y;
    int i = blockIdx.x * 256 + threadIdx.x;
    if (i < NN) g_wptr[dir][i] += g_bsum[dir][i / SCAN_BLK];
}

// ---------------- 4. scatter edges into CSR (4 edges/thread) ----------------
__global__ void k_scatter(const void* __restrict__ ei) {
    int base = (blockIdx.x * blockDim.x + threadIdx.x) * 4;
    if (base >= NE) return;
    int s[4], d[4];
    if (g_is64) {
        const long long* p = (const long long*)ei;
        #pragma unroll
        for (int k = 0; k < 4; k++) { s[k] = (int)p[base + k]; d[k] = (int)p[NE + base + k]; }
    } else {
        const int* p = (const int*)ei;
        int4 sv = *(const int4*)(p + base);
        int4 dv = *(const int4*)(p + NE + base);
        s[0] = sv.x; s[1] = sv.y; s[2] = sv.z; s[3] = sv.w;
        d[0] = dv.x; d[1] = dv.y; d[2] = dv.z; d[3] = dv.w;
    }
    #pragma unroll
    for (int k = 0; k < 4; k++) {
        if ((unsigned)s[k] < NN && (unsigned)d[k] < NN) {
            int p0 = atomicAdd(&g_wptr[0][d[k]], 1);
            g_adj[0][p0] = s[k];
            int p1 = atomicAdd(&g_wptr[1][s[k]], 1);
            g_adj[1][p1] = d[k];
        }
    }
}

// ---------------- 5. fused attention-vector precompute ----------------
__global__ void k_prep(const float* __restrict__ Wsrc, const float* __restrict__ Wdst,
                       const float* __restrict__ attS, const float* __restrict__ attD) {
    int k = threadIdx.x;
    float a0 = 0.f, a1 = 0.f, a2 = 0.f, a3 = 0.f;
    #pragma unroll 8
    for (int c = 0; c < 32; c++) {
        a0 = fmaf(Wsrc[k * 64 + c],      attS[c],      a0);
        a1 = fmaf(Wsrc[k * 64 + 32 + c], attS[32 + c], a1);
        a2 = fmaf(Wdst[k * 64 + c],      attD[c],      a2);
        a3 = fmaf(Wdst[k * 64 + 32 + c], attD[32 + c], a3);
    }
    g_wv[k] = make_float4(a0, a1, a2, a3);
}

// ---------------- 6. elu + x @ W_src + attention coefficients ----------------
__global__ void k_gemm(const float* __restrict__ hx, const float* __restrict__ tx,
                       const float* __restrict__ Wsrc, const float* __restrict__ attS) {
    __shared__ float Wc[128 * 64];   // [k][c]   32KB
    __shared__ float xt[32 * 128];   // [row][k] 16KB
    __shared__ float Av[64];
    int side = blockIdx.y;
    const float* X = side ? tx : hx;
    float* XS = g_xs[side];
    float2* ALS = g_als[side];
    float2* ALD = g_ald[side ^ 1];

    int tid = threadIdx.x;
    for (int i = tid; i < 128 * 64; i += 256) Wc[i] = Wsrc[i];
    if (tid < 64) Av[tid] = attS[tid];

    int warp = tid >> 5, lane = tid & 31;
    float4 wz, ww;
    {
        float4 w0 = g_wv[lane * 4 + 0];
        float4 w1 = g_wv[lane * 4 + 1];
        float4 w2 = g_wv[lane * 4 + 2];
        float4 w3 = g_wv[lane * 4 + 3];
        wz = make_float4(w0.z, w1.z, w2.z, w3.z);
        ww = make_float4(w0.w, w1.w, w2.w, w3.w);
    }

    int ntiles = (NN + 31) / 32;
    for (int tile = blockIdx.x; tile < ntiles; tile += gridDim.x) {
        __syncthreads();
        int r0 = tile * 32;
        for (int i = tid; i < 32 * 32; i += 256) {
            int row = i >> 5, q = i & 31;
            float4 v = make_float4(0.f, 0.f, 0.f, 0.f);
            int gr = r0 + row;
            if (gr < NN) v = ((const float4*)X)[gr * 32 + q];
            v.x = eluf(v.x); v.y = eluf(v.y); v.z = eluf(v.z); v.w = eluf(v.w);
            ((float4*)xt)[i] = v;
        }
        __syncthreads();

        int rb = warp * 4;
        const float* xr = xt + rb * 128;
        float2 a0 = {0.f,0.f}, a1 = {0.f,0.f}, a2 = {0.f,0.f}, a3 = {0.f,0.f};
        #pragma unroll 8
        for (int k = 0; k < 128; k += 4) {
            float4 x0 = *(const float4*)&xr[k];
            float4 x1 = *(const float4*)&xr[128 + k];
            float4 x2 = *(const float4*)&xr[256 + k];
            float4 x3 = *(const float4*)&xr[384 + k];
            #pragma unroll
            for (int j = 0; j < 4; j++) {
                float2 w = *(const float2*)&Wc[(k + j) * 64 + lane * 2];
                float v0 = j == 0 ? x0.x : j == 1 ? x0.y : j == 2 ? x0.z : x0.w;
                float v1 = j == 0 ? x1.x : j == 1 ? x1.y : j == 2 ? x1.z : x1.w;
                float v2 = j == 0 ? x2.x : j == 1 ? x2.y : j == 2 ? x2.z : x2.w;
                float v3 = j == 0 ? x3.x : j == 1 ? x3.y : j == 2 ? x3.z : x3.w;
                a0.x = fmaf(v0, w.x, a0.x); a0.y = fmaf(v0, w.y, a0.y);
                a1.x = fmaf(v1, w.x, a1.x); a1.y = fmaf(v1, w.y, a1.y);
                a2.x = fmaf(v2, w.x, a2.x); a2.y = fmaf(v2, w.y, a2.y);
                a3.x = fmaf(v3, w.x, a3.x); a3.y = fmaf(v3, w.y, a3.y);
            }
        }
        int g = r0 + rb;
        if (g + 0 < NN) ((float2*)XS)[(g + 0) * 32 + lane] = a0;
        if (g + 1 < NN) ((float2*)XS)[(g + 1) * 32 + lane] = a1;
        if (g + 2 < NN) ((float2*)XS)[(g + 2) * 32 + lane] = a2;
        if (g + 3 < NN) ((float2*)XS)[(g + 3) * 32 + lane] = a3;

        float avx = Av[lane * 2], avy = Av[lane * 2 + 1];
        #pragma unroll
        for (int r = 0; r < 4; r++) {
            float2 a = r == 0 ? a0 : r == 1 ? a1 : r == 2 ? a2 : a3;
            float v = a.x * avx + a.y * avy;
            #pragma unroll
            for (int off = 8; off; off >>= 1)
                v += __shfl_xor_sync(0xffffffffu, v, off);
            float v16 = __shfl_sync(0xffffffffu, v, 16);

            float4 xv = *(const float4*)&xr[r * 128 + lane * 4];
            float d0 = xv.x * wz.x + xv.y * wz.y + xv.z * wz.z + xv.w * wz.w;
            float d1 = xv.x * ww.x + xv.y * ww.y + xv.z * ww.z + xv.w * ww.w;
            #pragma unroll
            for (int off = 16; off; off >>= 1) {
                d0 += __shfl_xor_sync(0xffffffffu, d0, off);
                d1 += __shfl_xor_sync(0xffffffffu, d1, off);
            }
            if (lane == 0 && g + r < NN) {
                ALS[g + r] = make_float2(v, v16);
                ALD[g + r] = make_float2(d0, d1);
            }
        }
    }
}

// ---------------- 7. per-destination softmax aggregation (no max shift) ----------------
__global__ void k_agg(const float* __restrict__ bias, float* __restrict__ out) {
    int dir = blockIdx.y;
    int n = blockIdx.x * (blockDim.x >> 5) + (threadIdx.x >> 5);
    if (n >= NN) return;
    int lane = threadIdx.x & 31;
    int ch4 = lane & 15;
    bool head1 = (lane & 8) != 0;
    bool hiEdge = lane >= 16;

    const float*  xs  = g_xs[dir];
    const float2* als = g_als[dir];
    float2 aldn = g_ald[dir][n];
    float2 alsn = als[n];

    // self loop (softmax without max shift; |alpha| is O(10))
    float ps0 = __expf(lrelu(alsn.x + aldn.x));
    float ps1 = __expf(lrelu(alsn.y + aldn.y));
    float s0 = ps0, s1 = ps1;
    float psel = head1 ? ps1 : ps0;
    float4 acc = make_float4(0.f, 0.f, 0.f, 0.f);
    if (!hiEdge) {
        float4 xn = ((const float4*)xs)[n * 16 + ch4];
        acc = make_float4(psel * xn.x, psel * xn.y, psel * xn.z, psel * xn.w);
    }

    int deg = g_cnt[dir][n];
    int end = g_wptr[dir][n];
    const int* adj = g_adj[dir] + (end - deg);

    for (int base = 0; base < deg; base += 32) {
        int j = base + lane;
        int sv = 0;
        float p0 = 0.f, p1 = 0.f;
        if (j < deg) {
            sv = adj[j];
            float2 a = als[sv];
            p0 = __expf(lrelu(a.x + aldn.x));
            p1 = __expf(lrelu(a.y + aldn.y));
        }
        float t0 = p0, t1 = p1;
        #pragma unroll
        for (int off = 16; off; off >>= 1) {
            t0 += __shfl_xor_sync(0xffffffffu, t0, off);
            t1 += __shfl_xor_sync(0xffffffffu, t1, off);
        }
        s0 += t0;
        s1 += t1;

        int cnt = min(32, deg - base);
        int i = 0;
        int sel = hiEdge ? 1 : 0;
        // 8 edges/iter: 4 independent LDG.128 per lane in flight
        for (; i + 8 <= cnt; i += 8) {
            int   sA = __shfl_sync(0xffffffffu, sv, i + sel);
            float a0v = __shfl_sync(0xffffffffu, p0, i + sel);
            float a1v = __shfl_sync(0xffffffffu, p1, i + sel);
            int   sB = __shfl_sync(0xffffffffu, sv, i + 2 + sel);
            float b0v = __shfl_sync(0xffffffffu, p0, i + 2 + sel);
            float b1v = __shfl_sync(0xffffffffu, p1, i + 2 + sel);
            int   sC = __shfl_sync(0xffffffffu, sv, i + 4 + sel);
            float c0v = __shfl_sync(0xffffffffu, p0, i + 4 + sel);
            float c1v = __shfl_sync(0xffffffffu, p1, i + 4 + sel);
            int   sD = __shfl_sync(0xffffffffu, sv, i + 6 + sel);
            float d0v = __shfl_sync(0xffffffffu, p0, i + 6 + sel);
            float d1v = __shfl_sync(0xffffffffu, p1, i + 6 + sel);
            float4 xA = ((const float4*)xs)[sA * 16 + ch4];
            float4 xB = ((const float4*)xs)[sB * 16 + ch4];
            float4 xC = ((const float4*)xs)[sC * 16 + ch4];
            float4 xD = ((const float4*)xs)[sD * 16 + ch4];
            float wA = head1 ? a1v : a0v;
            float wB = head1 ? b1v : b0v;
            float wC = head1 ? c1v : c0v;
            float wD = head1 ? d1v : d0v;
            acc.x = fmaf(wA, xA.x, acc.x); acc.y = fmaf(wA, xA.y, acc.y);
            acc.z = fmaf(wA, xA.z, acc.z); acc.w = fmaf(wA, xA.w, acc.w);
            acc.x = fmaf(wB, xB.x, acc.x); acc.y = fmaf(wB, xB.y, acc.y);
            acc.z = fmaf(wB, xB.z, acc.z); acc.w = fmaf(wB, xB.w, acc.w);
            acc.x = fmaf(wC, xC.x, acc.x); acc.y = fmaf(wC, xC.y, acc.y);
            acc.z = fmaf(wC, xC.z, acc.z); acc.w = fmaf(wC, xC.w, acc.w);
            acc.x = fmaf(wD, xD.x, acc.x); acc.y = fmaf(wD, xD.y, acc.y);
            acc.z = fmaf(wD, xD.z, acc.z); acc.w = fmaf(wD, xD.w, acc.w);
        }
        for (; i < cnt; i += 2) {
            int idx = i + sel;
            int   s  = __shfl_sync(0xffffffffu, sv, idx);
            float w0 = __shfl_sync(0xffffffffu, p0, idx);
            float w1 = __shfl_sync(0xffffffffu, p1, idx);
            float w = head1 ? w1 : w0;
            if (hiEdge && i + 1 >= cnt) w = 0.f;   // odd tail: hi half idle
            float4 xv = ((const float4*)xs)[s * 16 + ch4];
            acc.x = fmaf(w, xv.x, acc.x);
            acc.y = fmaf(w, xv.y, acc.y);
            acc.z = fmaf(w, xv.z, acc.z);
            acc.w = fmaf(w, xv.w, acc.w);
        }
    }

    acc.x += __shfl_xor_sync(0xffffffffu, acc.x, 16);
    acc.y += __shfl_xor_sync(0xffffffffu, acc.y, 16);
    acc.z += __shfl_xor_sync(0xffffffffu, acc.z, 16);
    acc.w += __shfl_xor_sync(0xffffffffu, acc.w, 16);

    if (lane < 16) {
        float inv = 1.f / ((head1 ? s1 : s0) + 1e-16f);
        float4 b = ((const float4*)bias)[ch4];
        float4 o;
        o.x = acc.x * inv + b.x;
        o.y = acc.y * inv + b.y;
        o.z = acc.z * inv + b.z;
        o.w = acc.w * inv + b.w;
        float* op = out + (dir == 0 ? (size_t)NN * 64 : 0) + (size_t)n * 64;
        ((float4*)op)[ch4] = o;
    }
}

// ---------------- stream/event setup at static init (outside capture) ----------------
static cudaStream_t g_s2;
static cudaEvent_t  g_evF, g_evJ;
namespace {
struct _StreamInit {
    _StreamInit() {
        cudaStreamCreateWithFlags(&g_s2, cudaStreamNonBlocking);
        cudaEventCreateWithFlags(&g_evF, cudaEventDisableTiming);
        cudaEventCreateWithFlags(&g_evJ, cudaEventDisableTiming);
        k_warm<<<1, 1, 0, g_s2>>>();          // force lazy resource alloc now
        cudaStreamSynchronize(g_s2);
    }
} _streamInit;
}

// ---------------- launch ----------------
extern "C" void kernel_launch(void* const* d_in, const int* in_sizes, int n_in,
                              void* d_out, int out_size) {
    const float* hx   = (const float*)d_in[0];
    const float* tx   = (const float*)d_in[1];
    const void*  ei   = d_in[2];
    const float* Wsrc = (const float*)d_in[3];
    const float* Wdst = (const float*)d_in[4];
    const float* attS = (const float*)d_in[5];
    const float* attD = (const float*)d_in[6];
    const float* bias = (const float*)d_in[7];
    float* out = (float*)d_out;

    // fork: dense chain on g_s2, CSR chain on the main (capturing) stream
    cudaEventRecord(g_evF, 0);
    cudaStreamWaitEvent(g_s2, g_evF, 0);
    k_prep<<<1, 128, 0, g_s2>>>(Wsrc, Wdst, attS, attD);
    k_gemm<<<dim3(296, 2), 256, 0, g_s2>>>(hx, tx, Wsrc, attS);
    cudaEventRecord(g_evJ, g_s2);

    k_init<<<(2 * NN + 255) / 256, 256>>>(ei);
    k_hist<<<(NE / 4 + 255) / 256, 256>>>(ei);
    k_scan1<<<dim3(NSCAN_BLK, 2), SCAN_BLK>>>();
    k_scan2<<<1, 128>>>();
    k_scan3<<<dim3((NN + 255) / 256, 2), 256>>>();
    k_scatter<<<(NE / 4 + 255) / 256, 256>>>(ei);

    cudaStreamWaitEvent(0, g_evJ, 0);   // join
    k_agg<<<dim3((NN + 7) / 8, 2), 256>>>(bias, out);
}

// round 7
// speedup vs baseline: 1.6069x; 1.0925x over previous
#include <cuda_runtime.h>
#include <cuda_bf16.h>
#include <math.h>

#define NN 50000
#define NE 1600000
#define DD 128
#define HC 64    // H*C = 2*32
#define CAP 128  // max degree per bucket (mean 32, sigma ~5.7; overflow ~impossible)

// ---------------- scratch (no allocation allowed) ----------------
__device__ float  g_xs[2][NN * HC];     // side0: h@W_src, side1: t@W_src
__device__ float2 g_als[2][NN];         // xs·att_src per head, per side
__device__ float2 g_ald[2][NN];         // indexed by DIRECTION
__device__ float4 g_wv[DD];             // {ws_h0, ws_h1, wd_h0, wd_h1}
__device__ int    g_cnt[2][NN];
__device__ int    g_bkt[2][NN * CAP];   // fixed-capacity adjacency buckets (51MB)
__device__ int    g_is64;

__device__ __forceinline__ float eluf(float x) {
    return x > 0.f ? x : (__expf(x) - 1.f);
}
__device__ __forceinline__ float lrelu(float a) {
    return a > 0.f ? a : 0.2f * a;
}

__global__ void k_warm() {}

// ---------------- 1. zero counters + dtype detect ----------------
__global__ void k_init(const void* ei) {
    int i = blockIdx.x * blockDim.x + threadIdx.x;
    if (i < 2 * NN) ((int*)g_cnt)[i] = 0;
    if (blockIdx.x == 0 && threadIdx.x == 0) {
        const int4* p = (const int4*)ei;
        int nz = 0;
        #pragma unroll
        for (int k = 0; k < 32; k++) { int4 v = p[k]; nz |= v.y | v.w; }
        g_is64 = (nz == 0) ? 1 : 0;
    }
}

// ---------------- 2. single-pass bucket scatter (4 edges/thread) ----------------
// dir0: t_rep, bucket key = t-node d, payload = h-node s
// dir1: h_rep, bucket key = h-node s, payload = t-node d
__global__ void k_scatter(const void* __restrict__ ei) {
    int base = (blockIdx.x * blockDim.x + threadIdx.x) * 4;
    if (base >= NE) return;
    int s[4], d[4];
    if (g_is64) {
        const long long* p = (const long long*)ei;
        #pragma unroll
        for (int k = 0; k < 4; k++) { s[k] = (int)p[base + k]; d[k] = (int)p[NE + base + k]; }
    } else {
        const int* p = (const int*)ei;
        int4 sv = *(const int4*)(p + base);
        int4 dv = *(const int4*)(p + NE + base);
        s[0] = sv.x; s[1] = sv.y; s[2] = sv.z; s[3] = sv.w;
        d[0] = dv.x; d[1] = dv.y; d[2] = dv.z; d[3] = dv.w;
    }
    #pragma unroll
    for (int k = 0; k < 4; k++) {
        if ((unsigned)s[k] < NN && (unsigned)d[k] < NN) {
            int p0 = atomicAdd(&g_cnt[0][d[k]], 1);
            if (p0 < CAP) g_bkt[0][d[k] * CAP + p0] = s[k];
            int p1 = atomicAdd(&g_cnt[1][s[k]], 1);
            if (p1 < CAP) g_bkt[1][s[k] * CAP + p1] = d[k];
        }
    }
}

// ---------------- 3. fused attention-vector precompute ----------------
__global__ void k_prep(const float* __restrict__ Wsrc, const float* __restrict__ Wdst,
                       const float* __restrict__ attS, const float* __restrict__ attD) {
    int k = threadIdx.x;
    float a0 = 0.f, a1 = 0.f, a2 = 0.f, a3 = 0.f;
    #pragma unroll 8
    for (int c = 0; c < 32; c++) {
        a0 = fmaf(Wsrc[k * 64 + c],      attS[c],      a0);
        a1 = fmaf(Wsrc[k * 64 + 32 + c], attS[32 + c], a1);
        a2 = fmaf(Wdst[k * 64 + c],      attD[c],      a2);
        a3 = fmaf(Wdst[k * 64 + 32 + c], attD[32 + c], a3);
    }
    g_wv[k] = make_float4(a0, a1, a2, a3);
}

// ---------------- 4. elu + x @ W_src + attention coefficients ----------------
__global__ void k_gemm(const float* __restrict__ hx, const float* __restrict__ tx,
                       const float* __restrict__ Wsrc, const float* __restrict__ attS) {
    __shared__ float Wc[128 * 64];   // [k][c]   32KB
    __shared__ float xt[32 * 128];   // [row][k] 16KB
    __shared__ float Av[64];
    int side = blockIdx.y;
    const float* X = side ? tx : hx;
    float* XS = g_xs[side];
    float2* ALS = g_als[side];
    float2* ALD = g_ald[side ^ 1];

    int tid = threadIdx.x;
    for (int i = tid; i < 128 * 64; i += 256) Wc[i] = Wsrc[i];
    if (tid < 64) Av[tid] = attS[tid];

    int warp = tid >> 5, lane = tid & 31;
    float4 wz, ww;
    {
        float4 w0 = g_wv[lane * 4 + 0];
        float4 w1 = g_wv[lane * 4 + 1];
        float4 w2 = g_wv[lane * 4 + 2];
        float4 w3 = g_wv[lane * 4 + 3];
        wz = make_float4(w0.z, w1.z, w2.z, w3.z);
        ww = make_float4(w0.w, w1.w, w2.w, w3.w);
    }

    int ntiles = (NN + 31) / 32;
    for (int tile = blockIdx.x; tile < ntiles; tile += gridDim.x) {
        __syncthreads();
        int r0 = tile * 32;
        for (int i = tid; i < 32 * 32; i += 256) {
            int row = i >> 5, q = i & 31;
            float4 v = make_float4(0.f, 0.f, 0.f, 0.f);
            int gr = r0 + row;
            if (gr < NN) v = ((const float4*)X)[gr * 32 + q];
            v.x = eluf(v.x); v.y = eluf(v.y); v.z = eluf(v.z); v.w = eluf(v.w);
            ((float4*)xt)[i] = v;
        }
        __syncthreads();

        int rb = warp * 4;
        const float* xr = xt + rb * 128;
        float2 a0 = {0.f,0.f}, a1 = {0.f,0.f}, a2 = {0.f,0.f}, a3 = {0.f,0.f};
        #pragma unroll 8
        for (int k = 0; k < 128; k += 4) {
            float4 x0 = *(const float4*)&xr[k];
            float4 x1 = *(const float4*)&xr[128 + k];
            float4 x2 = *(const float4*)&xr[256 + k];
            float4 x3 = *(const float4*)&xr[384 + k];
            #pragma unroll
            for (int j = 0; j < 4; j++) {
                float2 w = *(const float2*)&Wc[(k + j) * 64 + lane * 2];
                float v0 = j == 0 ? x0.x : j == 1 ? x0.y : j == 2 ? x0.z : x0.w;
                float v1 = j == 0 ? x1.x : j == 1 ? x1.y : j == 2 ? x1.z : x1.w;
                float v2 = j == 0 ? x2.x : j == 1 ? x2.y : j == 2 ? x2.z : x2.w;
                float v3 = j == 0 ? x3.x : j == 1 ? x3.y : j == 2 ? x3.z : x3.w;
                a0.x = fmaf(v0, w.x, a0.x); a0.y = fmaf(v0, w.y, a0.y);
                a1.x = fmaf(v1, w.x, a1.x); a1.y = fmaf(v1, w.y, a1.y);
                a2.x = fmaf(v2, w.x, a2.x); a2.y = fmaf(v2, w.y, a2.y);
                a3.x = fmaf(v3, w.x, a3.x); a3.y = fmaf(v3, w.y, a3.y);
            }
        }
        int g = r0 + rb;
        if (g + 0 < NN) ((float2*)XS)[(g + 0) * 32 + lane] = a0;
        if (g + 1 < NN) ((float2*)XS)[(g + 1) * 32 + lane] = a1;
        if (g + 2 < NN) ((float2*)XS)[(g + 2) * 32 + lane] = a2;
        if (g + 3 < NN) ((float2*)XS)[(g + 3) * 32 + lane] = a3;

        float avx = Av[lane * 2], avy = Av[lane * 2 + 1];
        #pragma unroll
        for (int r = 0; r < 4; r++) {
            float2 a = r == 0 ? a0 : r == 1 ? a1 : r == 2 ? a2 : a3;
            float v = a.x * avx + a.y * avy;
            #pragma unroll
            for (int off = 8; off; off >>= 1)
                v += __shfl_xor_sync(0xffffffffu, v, off);
            float v16 = __shfl_sync(0xffffffffu, v, 16);

            float4 xv = *(const float4*)&xr[r * 128 + lane * 4];
            float d0 = xv.x * wz.x + xv.y * wz.y + xv.z * wz.z + xv.w * wz.w;
            float d1 = xv.x * ww.x + xv.y * ww.y + xv.z * ww.z + xv.w * ww.w;
            #pragma unroll
            for (int off = 16; off; off >>= 1) {
                d0 += __shfl_xor_sync(0xffffffffu, d0, off);
                d1 += __shfl_xor_sync(0xffffffffu, d1, off);
            }
            if (lane == 0 && g + r < NN) {
                ALS[g + r] = make_float2(v, v16);
                ALD[g + r] = make_float2(d0, d1);
            }
        }
    }
}

// ---------------- 5. per-destination softmax aggregation (no max shift) ----------------
__global__ void k_agg(const float* __restrict__ bias, float* __restrict__ out) {
    int dir = blockIdx.y;
    int n = blockIdx.x * (blockDim.x >> 5) + (threadIdx.x >> 5);
    if (n >= NN) return;
    int lane = threadIdx.x & 31;
    int ch4 = lane & 15;
    bool head1 = (lane & 8) != 0;
    bool hiEdge = lane >= 16;

    const float*  xs  = g_xs[dir];
    const float2* als = g_als[dir];
    float2 aldn = g_ald[dir][n];
    float2 alsn = als[n];

    // self loop (softmax without max shift; |alpha| is O(10))
    float ps0 = __expf(lrelu(alsn.x + aldn.x));
    float ps1 = __expf(lrelu(alsn.y + aldn.y));
    float s0 = ps0, s1 = ps1;
    float psel = head1 ? ps1 : ps0;
    float4 acc = make_float4(0.f, 0.f, 0.f, 0.f);
    if (!hiEdge) {
        float4 xn = ((const float4*)xs)[n * 16 + ch4];
        acc = make_float4(psel * xn.x, psel * xn.y, psel * xn.z, psel * xn.w);
    }

    int deg = min(g_cnt[dir][n], CAP);
    const int* adj = g_bkt[dir] + n * CAP;

    for (int base = 0; base < deg; base += 32) {
        int j = base + lane;
        int sv = 0;
        float p0 = 0.f, p1 = 0.f;
        if (j < deg) {
            sv = adj[j];
            float2 a = als[sv];
            p0 = __expf(lrelu(a.x + aldn.x));
            p1 = __expf(lrelu(a.y + aldn.y));
        }
        float t0 = p0, t1 = p1;
        #pragma unroll
        for (int off = 16; off; off >>= 1) {
            t0 += __shfl_xor_sync(0xffffffffu, t0, off);
            t1 += __shfl_xor_sync(0xffffffffu, t1, off);
        }
        s0 += t0;
        s1 += t1;

        int cnt = min(32, deg - base);
        int i = 0;
        int sel = hiEdge ? 1 : 0;
        // 8 edges/iter: 4 independent LDG.128 per lane in flight
        for (; i + 8 <= cnt; i += 8) {
            int   sA = __shfl_sync(0xffffffffu, sv, i + sel);
            float a0v = __shfl_sync(0xffffffffu, p0, i + sel);
            float a1v = __shfl_sync(0xffffffffu, p1, i + sel);
            int   sB = __shfl_sync(0xffffffffu, sv, i + 2 + sel);
            float b0v = __shfl_sync(0xffffffffu, p0, i + 2 + sel);
            float b1v = __shfl_sync(0xffffffffu, p1, i + 2 + sel);
            int   sC = __shfl_sync(0xffffffffu, sv, i + 4 + sel);
            float c0v = __shfl_sync(0xffffffffu, p0, i + 4 + sel);
            float c1v = __shfl_sync(0xffffffffu, p1, i + 4 + sel);
            int   sD = __shfl_sync(0xffffffffu, sv, i + 6 + sel);
            float d0v = __shfl_sync(0xffffffffu, p0, i + 6 + sel);
            float d1v = __shfl_sync(0xffffffffu, p1, i + 6 + sel);
            float4 xA = ((const float4*)xs)[sA * 16 + ch4];
            float4 xB = ((const float4*)xs)[sB * 16 + ch4];
            float4 xC = ((const float4*)xs)[sC * 16 + ch4];
            float4 xD = ((const float4*)xs)[sD * 16 + ch4];
            float wA = head1 ? a1v : a0v;
            float wB = head1 ? b1v : b0v;
            float wC = head1 ? c1v : c0v;
            float wD = head1 ? d1v : d0v;
            acc.x = fmaf(wA, xA.x, acc.x); acc.y = fmaf(wA, xA.y, acc.y);
            acc.z = fmaf(wA, xA.z, acc.z); acc.w = fmaf(wA, xA.w, acc.w);
            acc.x = fmaf(wB, xB.x, acc.x); acc.y = fmaf(wB, xB.y, acc.y);
            acc.z = fmaf(wB, xB.z, acc.z); acc.w = fmaf(wB, xB.w, acc.w);
            acc.x = fmaf(wC, xC.x, acc.x); acc.y = fmaf(wC, xC.y, acc.y);
            acc.z = fmaf(wC, xC.z, acc.z); acc.w = fmaf(wC, xC.w, acc.w);
            acc.x = fmaf(wD, xD.x, acc.x); acc.y = fmaf(wD, xD.y, acc.y);
            acc.z = fmaf(wD, xD.z, acc.z); acc.w = fmaf(wD, xD.w, acc.w);
        }
        for (; i < cnt; i += 2) {
            int idx = i + sel;
            int   s  = __shfl_sync(0xffffffffu, sv, idx);
            float w0 = __shfl_sync(0xffffffffu, p0, idx);
            float w1 = __shfl_sync(0xffffffffu, p1, idx);
            float w = head1 ? w1 : w0;
            if (hiEdge && i + 1 >= cnt) w = 0.f;   // odd tail: hi half idle
            float4 xv = ((const float4*)xs)[s * 16 + ch4];
            acc.x = fmaf(w, xv.x, acc.x);
            acc.y = fmaf(w, xv.y, acc.y);
            acc.z = fmaf(w, xv.z, acc.z);
            acc.w = fmaf(w, xv.w, acc.w);
        }
    }

    acc.x += __shfl_xor_sync(0xffffffffu, acc.x, 16);
    acc.y += __shfl_xor_sync(0xffffffffu, acc.y, 16);
    acc.z += __shfl_xor_sync(0xffffffffu, acc.z, 16);
    acc.w += __shfl_xor_sync(0xffffffffu, acc.w, 16);

    if (lane < 16) {
        float inv = 1.f / ((head1 ? s1 : s0) + 1e-16f);
        float4 b = ((const float4*)bias)[ch4];
        float4 o;
        o.x = acc.x * inv + b.x;
        o.y = acc.y * inv + b.y;
        o.z = acc.z * inv + b.z;
        o.w = acc.w * inv + b.w;
        float* op = out + (dir == 0 ? (size_t)NN * 64 : 0) + (size_t)n * 64;
        ((float4*)op)[ch4] = o;
    }
}

// ---------------- stream/event setup at static init (outside capture) ----------------
static cudaStream_t g_s2;
static cudaEvent_t  g_evF, g_evJ;
namespace {
struct _StreamInit {
    _StreamInit() {
        cudaStreamCreateWithFlags(&g_s2, cudaStreamNonBlocking);
        cudaEventCreateWithFlags(&g_evF, cudaEventDisableTiming);
        cudaEventCreateWithFlags(&g_evJ, cudaEventDisableTiming);
        k_warm<<<1, 1, 0, g_s2>>>();          // force lazy resource alloc now
        cudaStreamSynchronize(g_s2);
    }
} _streamInit;
}

// ---------------- launch ----------------
extern "C" void kernel_launch(void* const* d_in, const int* in_sizes, int n_in,
                              void* d_out, int out_size) {
    const float* hx   = (const float*)d_in[0];
    const float* tx   = (const float*)d_in[1];
    const void*  ei   = d_in[2];
    const float* Wsrc = (const float*)d_in[3];
    const float* Wdst = (const float*)d_in[4];
    const float* attS = (const float*)d_in[5];
    const float* attD = (const float*)d_in[6];
    const float* bias = (const float*)d_in[7];
    float* out = (float*)d_out;

    // fork: dense chain on g_s2, bucket-scatter chain on the main stream
    cudaEventRecord(g_evF, 0);
    cudaStreamWaitEvent(g_s2, g_evF, 0);
    k_prep<<<1, 128, 0, g_s2>>>(Wsrc, Wdst, attS, attD);
    k_gemm<<<dim3(296, 2), 256, 0, g_s2>>>(hx, tx, Wsrc, attS);
    cudaEventRecord(g_evJ, g_s2);

    k_init<<<(2 * NN + 255) / 256, 256>>>(ei);
    k_scatter<<<(NE / 4 + 255) / 256, 256>>>(ei);

    cudaStreamWaitEvent(0, g_evJ, 0);   // join
    k_agg<<<dim3((NN + 7) / 8, 2), 256>>>(bias, out);
}

// round 8
// speedup vs baseline: 1.6664x; 1.0370x over previous
#include <cuda_runtime.h>
#include <cuda_fp16.h>
#include <math.h>

#define NN 50000
#define NE 1600000
#define DD 128
#define HC 64    // H*C = 2*32
#define CAP 128  // max degree per bucket (mean 32, sigma ~5.7)

// ---------------- scratch (no allocation allowed) ----------------
__device__ __half  g_xs[2][NN * HC];    // fp16 message tables (6.4MB/side)
__device__ float2  g_als[2][NN];        // xs·att_src per head (fp32, pre-quantization)
__device__ float2  g_ald[2][NN];        // indexed by DIRECTION
__device__ float4  g_wv[DD];            // {ws_h0, ws_h1, wd_h0, wd_h1}
__device__ int     g_cnt[2][NN];
__device__ int     g_bkt[2][NN * CAP];  // fixed-capacity adjacency buckets
__device__ int     g_is64;

__device__ __forceinline__ float eluf(float x) {
    return x > 0.f ? x : (__expf(x) - 1.f);
}
__device__ __forceinline__ float lrelu(float a) {
    return a > 0.f ? a : 0.2f * a;
}

__global__ void k_warm() {}

// ---------------- 1. zero counters + dtype detect ----------------
__global__ void k_init(const void* ei) {
    int i = blockIdx.x * blockDim.x + threadIdx.x;
    if (i < 2 * NN) ((int*)g_cnt)[i] = 0;
    if (blockIdx.x == 0 && threadIdx.x == 0) {
        const int4* p = (const int4*)ei;
        int nz = 0;
        #pragma unroll
        for (int k = 0; k < 32; k++) { int4 v = p[k]; nz |= v.y | v.w; }
        g_is64 = (nz == 0) ? 1 : 0;
    }
}

// ---------------- 2. single-pass bucket scatter (4 edges/thread) ----------------
__global__ void k_scatter(const void* __restrict__ ei) {
    int base = (blockIdx.x * blockDim.x + threadIdx.x) * 4;
    if (base >= NE) return;
    int s[4], d[4];
    if (g_is64) {
        const long long* p = (const long long*)ei;
        #pragma unroll
        for (int k = 0; k < 4; k++) { s[k] = (int)p[base + k]; d[k] = (int)p[NE + base + k]; }
    } else {
        const int* p = (const int*)ei;
        int4 sv = *(const int4*)(p + base);
        int4 dv = *(const int4*)(p + NE + base);
        s[0] = sv.x; s[1] = sv.y; s[2] = sv.z; s[3] = sv.w;
        d[0] = dv.x; d[1] = dv.y; d[2] = dv.z; d[3] = dv.w;
    }
    #pragma unroll
    for (int k = 0; k < 4; k++) {
        if ((unsigned)s[k] < NN && (unsigned)d[k] < NN) {
            int p0 = atomicAdd(&g_cnt[0][d[k]], 1);
            if (p0 < CAP) g_bkt[0][d[k] * CAP + p0] = s[k];
            int p1 = atomicAdd(&g_cnt[1][s[k]], 1);
            if (p1 < CAP) g_bkt[1][s[k] * CAP + p1] = d[k];
        }
    }
}

// ---------------- 3. fused attention-vector precompute ----------------
__global__ void k_prep(const float* __restrict__ Wsrc, const float* __restrict__ Wdst,
                       const float* __restrict__ attS, const float* __restrict__ attD) {
    int k = threadIdx.x;
    float a0 = 0.f, a1 = 0.f, a2 = 0.f, a3 = 0.f;
    #pragma unroll 8
    for (int c = 0; c < 32; c++) {
        a0 = fmaf(Wsrc[k * 64 + c],      attS[c],      a0);
        a1 = fmaf(Wsrc[k * 64 + 32 + c], attS[32 + c], a1);
        a2 = fmaf(Wdst[k * 64 + c],      attD[c],      a2);
        a3 = fmaf(Wdst[k * 64 + 32 + c], attD[32 + c], a3);
    }
    g_wv[k] = make_float4(a0, a1, a2, a3);
}

// ---------------- 4. elu + x @ W_src + attention coefficients ----------------
__global__ void k_gemm(const float* __restrict__ hx, const float* __restrict__ tx,
                       const float* __restrict__ Wsrc, const float* __restrict__ attS) {
    __shared__ float Wc[128 * 64];   // [k][c]   32KB
    __shared__ float xt[32 * 128];   // [row][k] 16KB
    __shared__ float Av[64];
    int side = blockIdx.y;
    const float* X = side ? tx : hx;
    __half* XS = g_xs[side];
    float2* ALS = g_als[side];
    float2* ALD = g_ald[side ^ 1];

    int tid = threadIdx.x;
    for (int i = tid; i < 128 * 64; i += 256) Wc[i] = Wsrc[i];
    if (tid < 64) Av[tid] = attS[tid];

    int warp = tid >> 5, lane = tid & 31;
    float4 wz, ww;
    {
        float4 w0 = g_wv[lane * 4 + 0];
        float4 w1 = g_wv[lane * 4 + 1];
        float4 w2 = g_wv[lane * 4 + 2];
        float4 w3 = g_wv[lane * 4 + 3];
        wz = make_float4(w0.z, w1.z, w2.z, w3.z);
        ww = make_float4(w0.w, w1.w, w2.w, w3.w);
    }

    int ntiles = (NN + 31) / 32;
    for (int tile = blockIdx.x; tile < ntiles; tile += gridDim.x) {
        __syncthreads();
        int r0 = tile * 32;
        for (int i = tid; i < 32 * 32; i += 256) {
            int row = i >> 5, q = i & 31;
            float4 v = make_float4(0.f, 0.f, 0.f, 0.f);
            int gr = r0 + row;
            if (gr < NN) v = ((const float4*)X)[gr * 32 + q];
            v.x = eluf(v.x); v.y = eluf(v.y); v.z = eluf(v.z); v.w = eluf(v.w);
            ((float4*)xt)[i] = v;
        }
        __syncthreads();

        int rb = warp * 4;
        const float* xr = xt + rb * 128;
        float2 a0 = {0.f,0.f}, a1 = {0.f,0.f}, a2 = {0.f,0.f}, a3 = {0.f,0.f};
        #pragma unroll 8
        for (int k = 0; k < 128; k += 4) {
            float4 x0 = *(const float4*)&xr[k];
            float4 x1 = *(const float4*)&xr[128 + k];
            float4 x2 = *(const float4*)&xr[256 + k];
            float4 x3 = *(const float4*)&xr[384 + k];
            #pragma unroll
            for (int j = 0; j < 4; j++) {
                float2 w = *(const float2*)&Wc[(k + j) * 64 + lane * 2];
                float v0 = j == 0 ? x0.x : j == 1 ? x0.y : j == 2 ? x0.z : x0.w;
                float v1 = j == 0 ? x1.x : j == 1 ? x1.y : j == 2 ? x1.z : x1.w;
                float v2 = j == 0 ? x2.x : j == 1 ? x2.y : j == 2 ? x2.z : x2.w;
                float v3 = j == 0 ? x3.x : j == 1 ? x3.y : j == 2 ? x3.z : x3.w;
                a0.x = fmaf(v0, w.x, a0.x); a0.y = fmaf(v0, w.y, a0.y);
                a1.x = fmaf(v1, w.x, a1.x); a1.y = fmaf(v1, w.y, a1.y);
                a2.x = fmaf(v2, w.x, a2.x); a2.y = fmaf(v2, w.y, a2.y);
                a3.x = fmaf(v3, w.x, a3.x); a3.y = fmaf(v3, w.y, a3.y);
            }
        }
        int g = r0 + rb;
        if (g + 0 < NN) ((half2*)XS)[(g + 0) * 32 + lane] = __floats2half2_rn(a0.x, a0.y);
        if (g + 1 < NN) ((half2*)XS)[(g + 1) * 32 + lane] = __floats2half2_rn(a1.x, a1.y);
        if (g + 2 < NN) ((half2*)XS)[(g + 2) * 32 + lane] = __floats2half2_rn(a2.x, a2.y);
        if (g + 3 < NN) ((half2*)XS)[(g + 3) * 32 + lane] = __floats2half2_rn(a3.x, a3.y);

        float avx = Av[lane * 2], avy = Av[lane * 2 + 1];
        #pragma unroll
        for (int r = 0; r < 4; r++) {
            float2 a = r == 0 ? a0 : r == 1 ? a1 : r == 2 ? a2 : a3;
            float v = a.x * avx + a.y * avy;
            #pragma unroll
            for (int off = 8; off; off >>= 1)
                v += __shfl_xor_sync(0xffffffffu, v, off);
            float v16 = __shfl_sync(0xffffffffu, v, 16);

            float4 xv = *(const float4*)&xr[r * 128 + lane * 4];
            float d0 = xv.x * wz.x + xv.y * wz.y + xv.z * wz.z + xv.w * wz.w;
            float d1 = xv.x * ww.x + xv.y * ww.y + xv.z * ww.z + xv.w * ww.w;
            #pragma unroll
            for (int off = 16; off; off >>= 1) {
                d0 += __shfl_xor_sync(0xffffffffu, d0, off);
                d1 += __shfl_xor_sync(0xffffffffu, d1, off);
            }
            if (lane == 0 && g + r < NN) {
                ALS[g + r] = make_float2(v, v16);
                ALD[g + r] = make_float2(d0, d1);
            }
        }
    }
}

// ---------------- 5. aggregation: 8 lanes/edge, 4 edges in parallel ----------------
// lane&7 = 8-channel group (16B of fp16), lane>>3 = edge-within-quad
__device__ __forceinline__ void fma8(float* a, float w, uint4 r) {
    float2 f0 = __half22float2(*(__half2*)&r.x);
    float2 f1 = __half22float2(*(__half2*)&r.y);
    float2 f2 = __half22float2(*(__half2*)&r.z);
    float2 f3 = __half22float2(*(__half2*)&r.w);
    a[0] = fmaf(w, f0.x, a[0]); a[1] = fmaf(w, f0.y, a[1]);
    a[2] = fmaf(w, f1.x, a[2]); a[3] = fmaf(w, f1.y, a[3]);
    a[4] = fmaf(w, f2.x, a[4]); a[5] = fmaf(w, f2.y, a[5]);
    a[6] = fmaf(w, f3.x, a[6]); a[7] = fmaf(w, f3.y, a[7]);
}

__global__ void k_agg(const float* __restrict__ bias, float* __restrict__ out) {
    int dir = blockIdx.y;
    int n = blockIdx.x * (blockDim.x >> 5) + (threadIdx.x >> 5);
    if (n >= NN) return;
    int lane = threadIdx.x & 31;
    int ch8 = lane & 7;              // uint4 index within the 64-half row
    int q   = lane >> 3;             // edge slot 0-3
    bool head1 = ch8 >= 4;           // channels 32..63 -> head 1

    const __half*  xs  = g_xs[dir];
    const float2* als = g_als[dir];
    float2 aldn = g_ald[dir][n];
    float2 alsn = als[n];

    // self loop (no max shift; |alpha| is O(10))
    float ps0 = __expf(lrelu(alsn.x + aldn.x));
    float ps1 = __expf(lrelu(alsn.y + aldn.y));
    float s0 = ps0, s1 = ps1;
    float a[8] = {0.f,0.f,0.f,0.f,0.f,0.f,0.f,0.f};
    if (q == 0) {
        uint4 xn = ((const uint4*)xs)[n * 8 + ch8];
        fma8(a, head1 ? ps1 : ps0, xn);
    }

    int deg = min(g_cnt[dir][n], CAP);
    const int* adj = g_bkt[dir] + n * CAP;

    for (int base = 0; base < deg; base += 32) {
        int j = base + lane;
        int sv = 0;
        float p0 = 0.f, p1 = 0.f;
        if (j < deg) {
            sv = adj[j];
            float2 av = als[sv];
            p0 = __expf(lrelu(av.x + aldn.x));
            p1 = __expf(lrelu(av.y + aldn.y));
        }
        float t0 = p0, t1 = p1;
        #pragma unroll
        for (int off = 16; off; off >>= 1) {
            t0 += __shfl_xor_sync(0xffffffffu, t0, off);
            t1 += __shfl_xor_sync(0xffffffffu, t1, off);
        }
        s0 += t0;
        s1 += t1;

        int cnt = min(32, deg - base);
        int i = 0;
        // 8 edges / iteration: 2 independent row loads per lane
        for (; i + 8 <= cnt; i += 8) {
            int eA = i + q, eB = i + 4 + q;
            int   sA  = __shfl_sync(0xffffffffu, sv, eA);
            float a0v = __shfl_sync(0xffffffffu, p0, eA);
            float a1v = __shfl_sync(0xffffffffu, p1, eA);
            int   sB  = __shfl_sync(0xffffffffu, sv, eB);
            float b0v = __shfl_sync(0xffffffffu, p0, eB);
            float b1v = __shfl_sync(0xffffffffu, p1, eB);
            uint4 rA = ((const uint4*)xs)[sA * 8 + ch8];
            uint4 rB = ((const uint4*)xs)[sB * 8 + ch8];
            fma8(a, head1 ? a1v : a0v, rA);
            fma8(a, head1 ? b1v : b0v, rB);
        }
        for (; i < cnt; i += 4) {
            int e = i + q;
            int ee = e & 31;
            int   sA  = __shfl_sync(0xffffffffu, sv, ee);
            float w0  = __shfl_sync(0xffffffffu, p0, ee);
            float w1  = __shfl_sync(0xffffffffu, p1, ee);
            float w = head1 ? w1 : w0;
            if (e >= cnt) w = 0.f;
            uint4 rA = ((const uint4*)xs)[sA * 8 + ch8];
            fma8(a, w, rA);
        }
    }

    // combine the 4 edge-slot accumulators (reduce over lane bits 3,4)
    #pragma unroll
    for (int k = 0; k < 8; k++) {
        a[k] += __shfl_xor_sync(0xffffffffu, a[k], 8);
        a[k] += __shfl_xor_sync(0xffffffffu, a[k], 16);
    }

    if (lane < 8) {
        float inv = 1.f / ((head1 ? s1 : s0) + 1e-16f);
        float4 b0 = ((const float4*)bias)[ch8 * 2];
        float4 b1 = ((const float4*)bias)[ch8 * 2 + 1];
        float* op = out + (dir == 0 ? (size_t)NN * 64 : 0) + (size_t)n * 64;
        float4 o0, o1;
        o0.x = a[0] * inv + b0.x; o0.y = a[1] * inv + b0.y;
        o0.z = a[2] * inv + b0.z; o0.w = a[3] * inv + b0.w;
        o1.x = a[4] * inv + b1.x; o1.y = a[5] * inv + b1.y;
        o1.z = a[6] * inv + b1.z; o1.w = a[7] * inv + b1.w;
        ((float4*)op)[ch8 * 2]     = o0;
        ((float4*)op)[ch8 * 2 + 1] = o1;
    }
}

// ---------------- stream/event setup at static init (outside capture) ----------------
static cudaStream_t g_s2;
static cudaEvent_t  g_evF, g_evJ;
namespace {
struct _StreamInit {
    _StreamInit() {
        cudaStreamCreateWithFlags(&g_s2, cudaStreamNonBlocking);
        cudaEventCreateWithFlags(&g_evF, cudaEventDisableTiming);
        cudaEventCreateWithFlags(&g_evJ, cudaEventDisableTiming);
        k_warm<<<1, 1, 0, g_s2>>>();
        cudaStreamSynchronize(g_s2);
    }
} _streamInit;
}

// ---------------- launch ----------------
extern "C" void kernel_launch(void* const* d_in, const int* in_sizes, int n_in,
                              void* d_out, int out_size) {
    const float* hx   = (const float*)d_in[0];
    const float* tx   = (const float*)d_in[1];
    const void*  ei   = d_in[2];
    const float* Wsrc = (const float*)d_in[3];
    const float* Wdst = (const float*)d_in[4];
    const float* attS = (const float*)d_in[5];
    const float* attD = (const float*)d_in[6];
    const float* bias = (const float*)d_in[7];
    float* out = (float*)d_out;

    // fork: dense chain on g_s2, bucket-scatter chain on the main stream
    cudaEventRecord(g_evF, 0);
    cudaStreamWaitEvent(g_s2, g_evF, 0);
    k_prep<<<1, 128, 0, g_s2>>>(Wsrc, Wdst, attS, attD);
    k_gemm<<<dim3(296, 2), 256, 0, g_s2>>>(hx, tx, Wsrc, attS);
    cudaEventRecord(g_evJ, g_s2);

    k_init<<<(2 * NN + 255) / 256, 256>>>(ei);
    k_scatter<<<(NE / 4 + 255) / 256, 256>>>(ei);

    cudaStreamWaitEvent(0, g_evJ, 0);   // join
    k_agg<<<dim3((NN + 7) / 8, 2), 256>>>(bias, out);
}